// round 3
// baseline (speedup 1.0000x reference)
#include <cuda_runtime.h>
#include <math.h>

#define Bn 8
#define Sn 2048
#define Dn 2048
#define SMASK 2047
#define IR2 0.70710678118654752f
#define C22 0.35355339059327379f
#define EPSF 1e-8f
#define CFLF 0.4f
#define SQRTD 45.254833995939045f

__device__ float g_rho_raw[Bn * Sn];
__device__ float g_pt[Bn * Sn];
__device__ float g_rhof[Bn * Sn];

// ------------------------------------------------------------------
// Kernel A: fused rho_raw = ||haar_dwt(x)||_2 over D, and per_token = x.w
// One block per (b, group of 8 rows). Reads x exactly once.
// ------------------------------------------------------------------
__global__ void __launch_bounds__(256) kA(const float* __restrict__ x,
                                          const float* __restrict__ w) {
  int blk = blockIdx.x;
  int b = blk >> 8, k = blk & 255;
  const float4* base = (const float4*)(x + ((size_t)b * Sn + (size_t)k * 8) * Dn);
  const float4* w4 = (const float4*)w;

  float acc[16];
#pragma unroll
  for (int q = 0; q < 16; q++) acc[q] = 0.f;

  for (int c = threadIdx.x; c < Dn / 4; c += 256) {
    float4 xr[8];
#pragma unroll
    for (int j = 0; j < 8; j++) xr[j] = base[j * (Dn / 4) + c];
    float4 wv = w4[c];
#pragma unroll
    for (int comp = 0; comp < 4; comp++) {
      float v0 = ((const float*)&xr[0])[comp];
      float v1 = ((const float*)&xr[1])[comp];
      float v2 = ((const float*)&xr[2])[comp];
      float v3 = ((const float*)&xr[3])[comp];
      float v4 = ((const float*)&xr[4])[comp];
      float v5 = ((const float*)&xr[5])[comp];
      float v6 = ((const float*)&xr[6])[comp];
      float v7 = ((const float*)&xr[7])[comp];
      float wc = ((const float*)&wv)[comp];
      float e0 = v0 + v1, e1 = v2 + v3, e2 = v4 + v5, e3 = v6 + v7;
      float d10 = v0 - v1, d11 = v2 - v3, d12 = v4 - v5, d13 = v6 - v7;
      float a20 = e0 + e1, a21 = e2 + e3;
      float d20 = e0 - e1, d21 = e2 - e3;
      float a3 = a20 + a21, d3 = a20 - a21;
      acc[0] += a3 * a3;   acc[1] += d3 * d3;
      acc[2] += d20 * d20; acc[3] += d21 * d21;
      acc[4] += d10 * d10; acc[5] += d11 * d11;
      acc[6] += d12 * d12; acc[7] += d13 * d13;
      acc[8]  += v0 * wc; acc[9]  += v1 * wc; acc[10] += v2 * wc; acc[11] += v3 * wc;
      acc[12] += v4 * wc; acc[13] += v5 * wc; acc[14] += v6 * wc; acc[15] += v7 * wc;
    }
  }

  __shared__ float red[128];
  int lane = threadIdx.x & 31, wid = threadIdx.x >> 5;
#pragma unroll
  for (int q = 0; q < 16; q++) {
    float val = acc[q];
#pragma unroll
    for (int o = 16; o; o >>= 1) val += __shfl_xor_sync(0xffffffffu, val, o);
    if (lane == 0) red[q * 8 + wid] = val;
  }
  __syncthreads();
  if (threadIdx.x < 16) {
    float s2 = 0.f;
#pragma unroll
    for (int ww = 0; ww < 8; ww++) s2 += red[threadIdx.x * 8 + ww];
    int bs = b * Sn;
    int t = threadIdx.x;
    if (t == 0)      g_rho_raw[bs + k]                      = sqrtf(s2) * C22;
    else if (t == 1) g_rho_raw[bs + 256 + k]                = sqrtf(s2) * C22;
    else if (t < 4)  g_rho_raw[bs + 512 + 2 * k + (t - 2)]  = sqrtf(s2) * 0.5f;
    else if (t < 8)  g_rho_raw[bs + 1024 + 4 * k + (t - 4)] = sqrtf(s2) * IR2;
    else             g_pt[bs + 8 * k + (t - 8)] = s2;
  }
}

// ------------------------------------------------------------------
// Block-wide reductions for 1024 threads (32 warps)
// ------------------------------------------------------------------
__device__ __forceinline__ float blockSum(float val, float* sred) {
  unsigned lane = threadIdx.x & 31u, wid = threadIdx.x >> 5;
#pragma unroll
  for (int o = 16; o; o >>= 1) val += __shfl_xor_sync(0xffffffffu, val, o);
  if (lane == 0) sred[wid] = val;
  __syncthreads();
  if (wid == 0) {
    float t = sred[lane];
#pragma unroll
    for (int o = 16; o; o >>= 1) t += __shfl_xor_sync(0xffffffffu, t, o);
    if (lane == 0) sred[32] = t;
  }
  __syncthreads();
  float r = sred[32];
  __syncthreads();
  return r;
}

__device__ __forceinline__ float blockMax(float val, float* sred) {
  unsigned lane = threadIdx.x & 31u, wid = threadIdx.x >> 5;
#pragma unroll
  for (int o = 16; o; o >>= 1) val = fmaxf(val, __shfl_xor_sync(0xffffffffu, val, o));
  if (lane == 0) sred[wid] = val;
  __syncthreads();
  if (wid == 0) {
    float t = sred[lane];
#pragma unroll
    for (int o = 16; o; o >>= 1) t = fmaxf(t, __shfl_xor_sync(0xffffffffu, t, o));
    if (lane == 0) sred[32] = t;
  }
  __syncthreads();
  float r = sred[32];
  __syncthreads();
  return r;
}

__device__ __forceinline__ float blockMaxIdx(float v, int idx, float* sv, int* si,
                                             int* outIdx) {
  unsigned lane = threadIdx.x & 31u, wid = threadIdx.x >> 5;
#pragma unroll
  for (int o = 16; o; o >>= 1) {
    float ov = __shfl_xor_sync(0xffffffffu, v, o);
    int oi = __shfl_xor_sync(0xffffffffu, idx, o);
    if (ov > v || (ov == v && oi < idx)) { v = ov; idx = oi; }
  }
  if (lane == 0) { sv[wid] = v; si[wid] = idx; }
  __syncthreads();
  if (wid == 0) {
    v = sv[lane]; idx = si[lane];
#pragma unroll
    for (int o = 16; o; o >>= 1) {
      float ov = __shfl_xor_sync(0xffffffffu, v, o);
      int oi = __shfl_xor_sync(0xffffffffu, idx, o);
      if (ov > v || (ov == v && oi < idx)) { v = ov; idx = oi; }
    }
    if (lane == 0) { sv[32] = v; si[32] = idx; }
  }
  __syncthreads();
  v = sv[32];
  *outIdx = si[32];
  __syncthreads();
  return v;
}

// ------------------------------------------------------------------
// Leray projection: 50 Jacobi sweeps == exact 99-tap symmetric circular
// convolution (taps h in shared). out = in - grad1(conv(h, div1(in))).
// Self-adjoint, so the same routine is the VJP.
// ------------------------------------------------------------------
__device__ __forceinline__ void leray_apply(const float* __restrict__ in,
                                            float* __restrict__ outp,
                                            float* __restrict__ bv,
                                            float* __restrict__ pj,
                                            const float* __restrict__ h, int tid) {
#pragma unroll
  for (int e = 0; e < 2; e++) {
    int s = tid + (e << 10);
    bv[s] = in[s] - in[(s + SMASK) & SMASK];
  }
  __syncthreads();
#pragma unroll
  for (int e = 0; e < 2; e++) {
    int s = tid + (e << 10);
    float acc = 0.f;
    int basei = s + Sn - 49;
#pragma unroll 11
    for (int m = 0; m < 99; m++) acc = fmaf(h[m], bv[(basei + m) & SMASK], acc);
    pj[s] = acc;
  }
  __syncthreads();
#pragma unroll
  for (int e = 0; e < 2; e++) {
    int s = tid + (e << 10);
    outp[s] = in[s] - (pj[(s + 1) & SMASK] - pj[s]);
  }
  __syncthreads();
}

// ------------------------------------------------------------------
// Kernel B: full fluid/PC pipeline on (B,S). One block per batch,
// all state in shared memory.
// ------------------------------------------------------------------
__global__ void __launch_bounds__(1024, 1) kB(const float* __restrict__ phi_g) {
  int b = blockIdx.x;
  extern __shared__ float sm[];
  float* phi_s = sm;
  float* vv  = sm + 1 * Sn;
  float* rho = sm + 2 * Sn;
  float* u   = sm + 3 * Sn;
  float* up  = sm + 4 * Sn;
  float* bv  = sm + 5 * Sn;
  float* pj  = sm + 6 * Sn;
  float* r1  = sm + 7 * Sn;
  float* r2  = sm + 8 * Sn;
  float* r3  = sm + 9 * Sn;
  float* r4  = sm + 10 * Sn;
  float* gr  = sm + 11 * Sn;
  float* gy  = sm + 12 * Sn;
  float* gup = sm + 13 * Sn;
  float* Ft  = sm + 14 * Sn;
  float* yb  = sm + 15 * Sn;
  float* h   = sm + 16 * Sn;          // 112 floats (99 used)
  float* sred = h + 112;              // 36 floats
  int* sredi = (int*)(sred + 36);     // 36 ints
  int tid = threadIdx.x;

  // --- Jacobi-polynomial taps (fp64, per-tap closed recurrence) ---
  if (tid < 99) {
    int m = tid - 49;
    int am = m < 0 ? -m : m;
    double t = ldexp(1.0, -am);
    double acc = 0.0;
    for (int k = am; k <= 49; k += 2) {
      acc += t;
      int j = (k + m) >> 1;
      t = t * (double)((k + 1) * (k + 2)) / (4.0 * (double)((j + 1) * (k + 1 - j)));
    }
    h[tid] = (float)(-0.5 * acc);
  }

  // --- load phi, rho_raw; build v from per_token DWT ---
#pragma unroll
  for (int e = 0; e < 2; e++) {
    int s = tid + (e << 10);
    phi_s[s] = phi_g[s];
    rho[s] = g_rho_raw[b * Sn + s];
  }
  if (tid < 256) {
    const float* p = g_pt + b * Sn + tid * 8;
    float v0 = p[0], v1 = p[1], v2 = p[2], v3 = p[3];
    float v4 = p[4], v5 = p[5], v6 = p[6], v7 = p[7];
    float e0 = v0 + v1, e1 = v2 + v3, e2 = v4 + v5, e3 = v6 + v7;
    float d10 = v0 - v1, d11 = v2 - v3, d12 = v4 - v5, d13 = v6 - v7;
    float a20 = e0 + e1, a21 = e2 + e3;
    float d20 = e0 - e1, d21 = e2 - e3;
    float a3 = a20 + a21, d3 = a20 - a21;
    vv[tid]           = fabsf(a3) * C22 * SQRTD;
    vv[256 + tid]     = fabsf(d3) * C22 * SQRTD;
    vv[512 + 2 * tid]     = fabsf(d20) * 0.5f * SQRTD;
    vv[512 + 2 * tid + 1] = fabsf(d21) * 0.5f * SQRTD;
    vv[1024 + 4 * tid]     = fabsf(d10) * IR2 * SQRTD;
    vv[1024 + 4 * tid + 1] = fabsf(d11) * IR2 * SQRTD;
    vv[1024 + 4 * tid + 2] = fabsf(d12) * IR2 * SQRTD;
    vv[1024 + 4 * tid + 3] = fabsf(d13) * IR2 * SQRTD;
  }
  __syncthreads();
  // normalize v and rho  (abs+eps then / sum)
  {
    float ls = (vv[tid] + EPSF) + (vv[tid + 1024] + EPSF);
    float Sv = blockSum(ls, sred);
#pragma unroll
    for (int e = 0; e < 2; e++) { int s = tid + (e << 10); vv[s] = (vv[s] + EPSF) / Sv; }
    float lr = (rho[tid] + EPSF) + (rho[tid + 1024] + EPSF);
    float Sr = blockSum(lr, sred);
#pragma unroll
    for (int e = 0; e < 2; e++) { int s = tid + (e << 10); rho[s] = (rho[s] + EPSF) / Sr; }
    __syncthreads();
  }

  float* const rs[5] = {rho, r1, r2, r3, r4};

  for (int ko = 0; ko < 3; ko++) {
    // ---- reaction ----
#pragma unroll
    for (int e = 0; e < 2; e++) {
      int s = tid + (e << 10);
      float rv = rho[s];
      yb[s] = rv * expf(-0.1f * (phi_s[s] + logf(rv))) + EPSF;
    }
    {
      float Sw = blockSum(yb[tid] + yb[tid + 1024], sred);
#pragma unroll
      for (int e = 0; e < 2; e++) { int s = tid + (e << 10); rho[s] = yb[s] / Sw; }
      __syncthreads();
    }

    // ---- mpc: u0 = grad1(v), 5 hand-VJP gradient steps ----
#pragma unroll
    for (int e = 0; e < 2; e++) {
      int s = tid + (e << 10);
      u[s] = vv[(s + 1) & SMASK] - vv[s];
    }
    __syncthreads();

    for (int it = 0; it < 5; it++) {
      leray_apply(u, up, bv, pj, h, tid);
      float a0 = fabsf(up[tid]), a1 = fabsf(up[tid + 1024]);
      int midx = (a0 >= a1) ? tid : tid + 1024;
      int imax;
      float m = blockMaxIdx(fmaxf(a0, a1), midx, sred, sredi, &imax);
      float dt = CFLF / (m + EPSF);

      // forward horizon (keep all r_h and stage sums)
      float swv[4];
#pragma unroll
      for (int h4 = 0; h4 < 4; h4++) {
        float* ri = rs[h4]; float* ro = rs[h4 + 1];
#pragma unroll
        for (int e = 0; e < 2; e++) {
          int s = tid + (e << 10);
          int sp = (s + 1) & SMASK, sm1 = (s + SMASK) & SMASK;
          float us = up[s], usm = up[sm1];
          float F  = us  > 0.f ? us * ri[s]   : us * ri[sp];
          float Fm = usm > 0.f ? usm * ri[sm1] : usm * ri[s];
          float y = ri[s] - dt * (F - Fm);
          ro[s] = fabsf(y) + EPSF;
        }
        float Sw = blockSum(ro[tid] + ro[tid + 1024], sred);
        swv[h4] = Sw;
#pragma unroll
        for (int e = 0; e < 2; e++) { int s = tid + (e << 10); ro[s] /= Sw; }
        __syncthreads();
      }

      // backward: seed (1-v)/B
#pragma unroll
      for (int e = 0; e < 2; e++) {
        int s = tid + (e << 10);
        gr[s] = (1.f - vv[s]) * 0.125f;
        gup[s] = 0.f;
      }
      __syncthreads();
      float gdt = 0.f;
#pragma unroll
      for (int h4 = 3; h4 >= 0; h4--) {
        float* ri = rs[h4]; float* ro = rs[h4 + 1];
        float Sw = swv[h4];
        // recompute F, y
#pragma unroll
        for (int e = 0; e < 2; e++) {
          int s = tid + (e << 10);
          int sp = (s + 1) & SMASK, sm1 = (s + SMASK) & SMASK;
          float us = up[s], usm = up[sm1];
          float F  = us  > 0.f ? us * ri[s]   : us * ri[sp];
          float Fm = usm > 0.f ? usm * ri[sm1] : usm * ri[s];
          Ft[s] = F;
          yb[s] = ri[s] - dt * (F - Fm);
        }
        float dot = blockSum(gr[tid] * ro[tid] + gr[tid + 1024] * ro[tid + 1024], sred);
#pragma unroll
        for (int e = 0; e < 2; e++) {
          int s = tid + (e << 10);
          float gw = (gr[s] - dot) / Sw;
          float ys = yb[s];
          gy[s] = ys > 0.f ? gw : (ys < 0.f ? -gw : 0.f);
        }
        __syncthreads();
        float part = 0.f;
#pragma unroll
        for (int e = 0; e < 2; e++) {
          int s = tid + (e << 10);
          int sp = (s + 1) & SMASK, sm1 = (s + SMASK) & SMASK;
          float gys = gy[s];
          float gFs = dt * (gy[sp] - gys);
          float gFm = dt * (gys - gy[sm1]);
          part += gys * (Ft[sm1] - Ft[s]);
          float us = up[s], usm = up[sm1];
          gup[s] += gFs * (us > 0.f ? ri[s] : ri[sp]);
          gr[s] = gys + (us > 0.f ? us * gFs : 0.f) + (usm > 0.f ? 0.f : usm * gFm);
        }
        gdt += blockSum(part, sred);
      }
      // dt/max path
      float gm = gdt * (-dt * dt * (1.f / CFLF));
      if (tid == (imax & 1023)) {
        float uv = up[imax];
        gup[imax] += gm * (uv > 0.f ? 1.f : (uv < 0.f ? -1.f : 0.f));
      }
      __syncthreads();
      // adjoint Leray (= Leray), gradient step
      leray_apply(gup, gy, bv, pj, h, tid);
#pragma unroll
      for (int e = 0; e < 2; e++) { int s = tid + (e << 10); u[s] -= 0.1f * gy[s]; }
      __syncthreads();
    }

    // ---- outer: u = leray(mpc), advect rho with kappa ----
    leray_apply(u, up, bv, pj, h, tid);
    float m = blockMax(fmaxf(fabsf(up[tid]), fabsf(up[tid + 1024])), sred);
    float dt = CFLF / (m + EPSF);
    float kap = (ko == 0) ? 0.01f : ((ko == 1) ? 0.005f : 0.0f);
#pragma unroll
    for (int e = 0; e < 2; e++) {
      int s = tid + (e << 10);
      int sp = (s + 1) & SMASK, sm1 = (s + SMASK) & SMASK;
      float us = up[s], usm = up[sm1];
      float F  = us  > 0.f ? us * rho[s]   : us * rho[sp];
      float Fm = usm > 0.f ? usm * rho[sm1] : usm * rho[s];
      float y = rho[s] - dt * (F - Fm) + kap * dt * (rho[sp] + rho[sm1] - 2.f * rho[s]);
      yb[s] = fabsf(y) + EPSF;
    }
    {
      float Sw = blockSum(yb[tid] + yb[tid + 1024], sred);
#pragma unroll
      for (int e = 0; e < 2; e++) { int s = tid + (e << 10); rho[s] = yb[s] / Sw; }
      __syncthreads();
    }
  }

  // ---- final: rho_f = (rho + 0.1 v) / sum ----
#pragma unroll
  for (int e = 0; e < 2; e++) {
    int s = tid + (e << 10);
    yb[s] = rho[s] + 0.1f * vv[s];
  }
  float Sf = blockSum(yb[tid] + yb[tid + 1024], sred);
#pragma unroll
  for (int e = 0; e < 2; e++) {
    int s = tid + (e << 10);
    g_rhof[b * Sn + s] = yb[s] / Sf;
  }
}

// ------------------------------------------------------------------
// Kernel C: out = haar_idwt(rho_f[:, :, None] * band_w[BAND_IDX]).
// Each output row = 4-term combination of band_w rows; one block per
// (b, group of 8 output rows). Pure streaming write.
// ------------------------------------------------------------------
__global__ void __launch_bounds__(256) kC(const float* __restrict__ bw,
                                          float* __restrict__ out) {
  int blk = blockIdx.x;
  int b = blk >> 8, k = blk & 255;
  const float* rf = g_rhof + b * Sn;
  float A  = rf[k] * C22;
  float E  = rf[256 + k] * C22;
  float C0 = rf[512 + 2 * k] * 0.5f;
  float C1 = rf[512 + 2 * k + 1] * 0.5f;
  float D0 = rf[1024 + 4 * k] * IR2;
  float D1 = rf[1024 + 4 * k + 1] * IR2;
  float D2 = rf[1024 + 4 * k + 2] * IR2;
  float D3 = rf[1024 + 4 * k + 3] * IR2;

  float s1[8], s2[8], s3[8];
#pragma unroll
  for (int j = 0; j < 8; j++) {
    float Ej = (j < 4) ? E : -E;
    float Cj = (j < 4) ? C0 : C1;
    if ((j & 3) >= 2) Cj = -Cj;
    float Dj = (j >> 1) == 0 ? D0 : ((j >> 1) == 1 ? D1 : ((j >> 1) == 2 ? D2 : D3));
    if (j & 1) Dj = -Dj;
    s1[j] = Ej; s2[j] = Cj; s3[j] = Dj;
  }

  const float4* b0 = (const float4*)bw;
  const float4* b1 = (const float4*)(bw + Dn);
  const float4* b2 = (const float4*)(bw + 2 * Dn);
  const float4* b3 = (const float4*)(bw + 3 * Dn);
  float4* ob = (float4*)(out + ((size_t)b * Sn + (size_t)k * 8) * Dn);

  for (int c = threadIdx.x; c < Dn / 4; c += 256) {
    float4 w0 = b0[c], w1 = b1[c], w2 = b2[c], w3 = b3[c];
#pragma unroll
    for (int j = 0; j < 8; j++) {
      float4 o;
      o.x = A * w0.x + s1[j] * w1.x + s2[j] * w2.x + s3[j] * w3.x;
      o.y = A * w0.y + s1[j] * w1.y + s2[j] * w2.y + s3[j] * w3.y;
      o.z = A * w0.z + s1[j] * w1.z + s2[j] * w2.z + s3[j] * w3.z;
      o.w = A * w0.w + s1[j] * w1.w + s2[j] * w2.w + s3[j] * w3.w;
      ob[j * (Dn / 4) + c] = o;
    }
  }
}

// ------------------------------------------------------------------
#define SMEMB ((16 * Sn + 112 + 36) * 4 + 36 * 4)

extern "C" void kernel_launch(void* const* d_in, const int* in_sizes, int n_in,
                              void* d_out, int out_size) {
  const float* x   = (const float*)d_in[0];
  const float* w   = (const float*)d_in[1];
  const float* phi = (const float*)d_in[2];
  const float* bw  = (const float*)d_in[3];
  float* out = (float*)d_out;

  cudaFuncSetAttribute((const void*)kB, cudaFuncAttributeMaxDynamicSharedMemorySize, SMEMB);

  kA<<<Bn * 256, 256>>>(x, w);
  kB<<<Bn, 1024, SMEMB>>>(phi);
  kC<<<Bn * 256, 256>>>(bw, out);
}

// round 6
// speedup vs baseline: 1.4750x; 1.4750x over previous
#include <cuda_runtime.h>
#include <math.h>

#define Bn 8
#define Sn 2048
#define Dn 2048
#define SMASK 2047
#define IR2 0.70710678118654752f
#define C22 0.35355339059327379f
#define EPSF 1e-8f
#define CFLF 0.4f
#define SQRTD 45.254833995939045f

__device__ float g_rho_raw[Bn * Sn];
__device__ float g_pt[Bn * Sn];
__device__ float g_rhof[Bn * Sn];

// ------------------------------------------------------------------
// Compile-time Leray taps.
// 50 Jacobi sweeps from p0=0:  p = -1/2 * sum_{k=0}^{49} A^k b,  A=(S+ + S-)/2
// h(m) = -1/2 * sum_{k=|m|,step2}^{49} 2^-k C(k,(k+m)/2)
// Full Leray operator: out[s] = sum_m L(m) u[s+m],
//   L(m) = delta(m) + 2h(m) - h(m-1) - h(m+1)      (101 taps, m in [-50,50])
// Evaluated at HOST compile time into a __constant__ float array.
// ------------------------------------------------------------------
struct TapsF { float L[101]; };
__host__ __device__ constexpr TapsF makeTapsF() {
  double h[103] = {};
  for (int m = -49; m <= 49; m++) {
    int am = m < 0 ? -m : m;
    double term = 1.0;
    for (int i = 0; i < am; i++) term *= 0.5;
    double acc = 0.0;
    for (int k = am; k <= 49; k += 2) {
      acc += term;
      int j = (k + m) / 2;
      term = term * (double)((k + 1) * (k + 2)) / (4.0 * (double)((j + 1) * (k + 1 - j)));
    }
    h[51 + m] = -0.5 * acc;
  }
  TapsF t{};
  for (int m = -50; m <= 50; m++) {
    double v = 2.0 * h[51 + m] - h[51 + m - 1] - h[51 + m + 1];
    t.L[50 + m] = (float)((m == 0 ? 1.0 : 0.0) + v);
  }
  return t;
}
__constant__ TapsF TAPS = makeTapsF();

// Single-pass Leray conv for one output pair (s0, s0+1), s0 even.
__device__ __forceinline__ float2 conv101(const float* __restrict__ in, int s0) {
  float o0 = 0.f, o1 = 0.f;
  const int base = s0 + (Sn - 50);
#pragma unroll
  for (int j = 0; j <= 50; j++) {
    int e = (base + 2 * j) & SMASK;
    float2 w = *(const float2*)(in + e);
    const float tA = TAPS.L[2 * j];
    o0 = fmaf(tA, w.x, o0);
    o1 = fmaf(tA, w.y, o1);
    if (j <= 49) { const float tB = TAPS.L[2 * j + 1]; o0 = fmaf(tB, w.y, o0); }
    if (j >= 1)  { const float tC = TAPS.L[2 * j - 1]; o1 = fmaf(tC, w.x, o1); }
  }
  return make_float2(o0, o1);
}

// ------------------------------------------------------------------
// Kernel A: fused rho_raw = ||haar_dwt(x)||_2 over D, and per_token = x.w
// ------------------------------------------------------------------
__global__ void __launch_bounds__(256) kA(const float* __restrict__ x,
                                          const float* __restrict__ w) {
  int blk = blockIdx.x;
  int b = blk >> 8, k = blk & 255;
  const float4* base = (const float4*)(x + ((size_t)b * Sn + (size_t)k * 8) * Dn);
  const float4* w4 = (const float4*)w;

  float acc[16];
#pragma unroll
  for (int q = 0; q < 16; q++) acc[q] = 0.f;

  for (int c = threadIdx.x; c < Dn / 4; c += 256) {
    float4 xr[8];
#pragma unroll
    for (int j = 0; j < 8; j++) xr[j] = __ldcs(base + j * (Dn / 4) + c);
    float4 wv = w4[c];
#pragma unroll
    for (int comp = 0; comp < 4; comp++) {
      float v0 = ((const float*)&xr[0])[comp];
      float v1 = ((const float*)&xr[1])[comp];
      float v2 = ((const float*)&xr[2])[comp];
      float v3 = ((const float*)&xr[3])[comp];
      float v4 = ((const float*)&xr[4])[comp];
      float v5 = ((const float*)&xr[5])[comp];
      float v6 = ((const float*)&xr[6])[comp];
      float v7 = ((const float*)&xr[7])[comp];
      float wc = ((const float*)&wv)[comp];
      float e0 = v0 + v1, e1 = v2 + v3, e2 = v4 + v5, e3 = v6 + v7;
      float d10 = v0 - v1, d11 = v2 - v3, d12 = v4 - v5, d13 = v6 - v7;
      float a20 = e0 + e1, a21 = e2 + e3;
      float d20 = e0 - e1, d21 = e2 - e3;
      float a3 = a20 + a21, d3 = a20 - a21;
      acc[0] += a3 * a3;   acc[1] += d3 * d3;
      acc[2] += d20 * d20; acc[3] += d21 * d21;
      acc[4] += d10 * d10; acc[5] += d11 * d11;
      acc[6] += d12 * d12; acc[7] += d13 * d13;
      acc[8]  += v0 * wc; acc[9]  += v1 * wc; acc[10] += v2 * wc; acc[11] += v3 * wc;
      acc[12] += v4 * wc; acc[13] += v5 * wc; acc[14] += v6 * wc; acc[15] += v7 * wc;
    }
  }

  __shared__ float red[128];
  int lane = threadIdx.x & 31, wid = threadIdx.x >> 5;
#pragma unroll
  for (int q = 0; q < 16; q++) {
    float val = acc[q];
#pragma unroll
    for (int o = 16; o; o >>= 1) val += __shfl_xor_sync(0xffffffffu, val, o);
    if (lane == 0) red[q * 8 + wid] = val;
  }
  __syncthreads();
  if (threadIdx.x < 16) {
    float s2 = 0.f;
#pragma unroll
    for (int ww = 0; ww < 8; ww++) s2 += red[threadIdx.x * 8 + ww];
    int bs = b * Sn;
    int t = threadIdx.x;
    if (t == 0)      g_rho_raw[bs + k]                      = sqrtf(s2) * C22;
    else if (t == 1) g_rho_raw[bs + 256 + k]                = sqrtf(s2) * C22;
    else if (t < 4)  g_rho_raw[bs + 512 + 2 * k + (t - 2)]  = sqrtf(s2) * 0.5f;
    else if (t < 8)  g_rho_raw[bs + 1024 + 4 * k + (t - 4)] = sqrtf(s2) * IR2;
    else             g_pt[bs + 8 * k + (t - 8)] = s2;
  }
}

// ------------------------------------------------------------------
// One-sync reductions: warp-reduce -> store 32 partials -> (caller syncs)
// -> every thread scans all 32 (broadcast LDS).
// ------------------------------------------------------------------
__device__ __forceinline__ void redStoreSum(float v, float* buf, int lane, int wid) {
#pragma unroll
  for (int o = 16; o; o >>= 1) v += __shfl_xor_sync(0xffffffffu, v, o);
  if (lane == 0) buf[wid] = v;
}
__device__ __forceinline__ float readSum32(const float* buf) {
  float s0 = 0.f, s1 = 0.f, s2 = 0.f, s3 = 0.f;
#pragma unroll
  for (int i = 0; i < 8; i++) {
    s0 += buf[4 * i]; s1 += buf[4 * i + 1]; s2 += buf[4 * i + 2]; s3 += buf[4 * i + 3];
  }
  return (s0 + s1) + (s2 + s3);
}
__device__ __forceinline__ void redStoreMaxIdx(float v, int idx, float* bv, int* bi,
                                               int lane, int wid) {
#pragma unroll
  for (int o = 16; o; o >>= 1) {
    float ov = __shfl_xor_sync(0xffffffffu, v, o);
    int oi = __shfl_xor_sync(0xffffffffu, idx, o);
    if (ov > v || (ov == v && oi < idx)) { v = ov; idx = oi; }
  }
  if (lane == 0) { bv[wid] = v; bi[wid] = idx; }
}
__device__ __forceinline__ float readMax32(const float* bv, const int* bi, int* oi) {
  float m = -1e30f; int mi = 1 << 30;
#pragma unroll
  for (int i = 0; i < 32; i++) {
    float v = bv[i]; int ii = bi[i];
    if (v > m || (v == m && ii < mi)) { m = v; mi = ii; }
  }
  *oi = mi;
  return m;
}

// ------------------------------------------------------------------
// Kernel B: full fluid/PC pipeline. One block per batch, 1024 threads,
// thread t owns elements (2t, 2t+1). All state in shared memory.
// ------------------------------------------------------------------
__global__ void __launch_bounds__(1024, 1) kB(const float* __restrict__ phi_g) {
  int b = blockIdx.x;
  extern __shared__ float sm[];
  float* phi_s = sm + 0 * Sn;
  float* vv  = sm + 1 * Sn;
  float* rb0 = sm + 2 * Sn;   // rho z-buffer A
  float* rb1 = sm + 3 * Sn;   // rho z-buffer B
  float* u   = sm + 4 * Sn;
  float* up  = sm + 5 * Sn;
  float* z1  = sm + 6 * Sn;
  float* z2  = sm + 7 * Sn;
  float* z3  = sm + 8 * Sn;
  float* z4  = sm + 9 * Sn;
  float* gr  = sm + 10 * Sn;
  float* gy  = sm + 11 * Sn;
  float* gup = sm + 12 * Sn;
  float* Ft  = sm + 13 * Sn;
  float* yb  = sm + 14 * Sn;
  float* red = sm + 15 * Sn;
  float* redMax = red;                 // 32
  int*   redIdx = (int*)(red + 32);    // 32
  float* redS   = red + 64;            // 4 x 32
  float* redDot = red + 192;           // 32
  float* redPart = red + 224;          // 32
  float* redR   = red + 256;           // 32  (reaction-output sum)
  float* redF   = red + 288;           // 32  (advect-output sum)

  const int tid = threadIdx.x;
  const int lane = tid & 31, wid = tid >> 5;
  const int s0 = 2 * tid, s1i = s0 + 1;
  const int smm = (s0 + SMASK) & SMASK;   // s0-1
  const int sp2 = (s0 + 2) & SMASK;       // s0+2

  // ---- I1: load phi, rho_raw (+eps); build v raw from per_token DWT ----
#pragma unroll
  for (int e = 0; e < 2; e++) {
    int s = tid + (e << 10);
    phi_s[s] = phi_g[s];
    rb0[s] = g_rho_raw[b * Sn + s] + EPSF;
  }
  if (tid < 256) {
    const float* p = g_pt + b * Sn + tid * 8;
    float v0 = p[0], v1 = p[1], v2 = p[2], v3 = p[3];
    float v4 = p[4], v5 = p[5], v6 = p[6], v7 = p[7];
    float e0 = v0 + v1, e1 = v2 + v3, e2 = v4 + v5, e3 = v6 + v7;
    float d10 = v0 - v1, d11 = v2 - v3, d12 = v4 - v5, d13 = v6 - v7;
    float a20 = e0 + e1, a21 = e2 + e3;
    float d20 = e0 - e1, d21 = e2 - e3;
    float a3 = a20 + a21, d3 = a20 - a21;
    vv[tid]               = fabsf(a3) * C22 * SQRTD;
    vv[256 + tid]         = fabsf(d3) * C22 * SQRTD;
    vv[512 + 2 * tid]     = fabsf(d20) * 0.5f * SQRTD;
    vv[512 + 2 * tid + 1] = fabsf(d21) * 0.5f * SQRTD;
    vv[1024 + 4 * tid]     = fabsf(d10) * IR2 * SQRTD;
    vv[1024 + 4 * tid + 1] = fabsf(d11) * IR2 * SQRTD;
    vv[1024 + 4 * tid + 2] = fabsf(d12) * IR2 * SQRTD;
    vv[1024 + 4 * tid + 3] = fabsf(d13) * IR2 * SQRTD;
  }
  __syncthreads();
  // ---- I2: partial sums (rho-with-eps -> redF, v-with-eps -> redR) ----
  redStoreSum(rb0[s0] + rb0[s1i], redF, lane, wid);
  redStoreSum((vv[s0] + EPSF) + (vv[s1i] + EPSF), redR, lane, wid);
  __syncthreads();
  // ---- I3: normalize v in place ----
  {
    float invSv = 1.f / readSum32(redR);
    vv[s0] = (vv[s0] + EPSF) * invSv;
    vv[s1i] = (vv[s1i] + EPSF) * invSv;
  }
  __syncthreads();

  float* rz = rb0;
  float* rzo = rb1;

  for (int ko = 0; ko < 3; ko++) {
    // ---- PR1: reaction (in place on rz, own pair) + u = grad1(v) ----
    {
      float invR = 1.f / readSum32(redF);
      float rv0 = rz[s0] * invR, rv1 = rz[s1i] * invR;
      float w0 = rv0 * expf(-0.1f * (phi_s[s0] + logf(rv0))) + EPSF;
      float w1 = rv1 * expf(-0.1f * (phi_s[s1i] + logf(rv1))) + EPSF;
      rz[s0] = w0; rz[s1i] = w1;
      redStoreSum(w0 + w1, redR, lane, wid);
      u[s0] = vv[s1i] - vv[s0];
      u[s1i] = vv[sp2] - vv[s1i];
    }
    __syncthreads();

    float invR0 = 0.f;
    float dt = 0.f;
    int imax = 0;

    for (int it = 0; it <= 5; it++) {
      // ---- P1: up = leray(u) (single conv) + max|up| w/ argmax ----
      if (it == 0) invR0 = 1.f / readSum32(redR);
      {
        float2 c = conv101(u, s0);
        up[s0] = c.x; up[s1i] = c.y;
        float a0 = fabsf(c.x), a1 = fabsf(c.y);
        float mv; int mi;
        if (a0 >= a1) { mv = a0; mi = s0; } else { mv = a1; mi = s1i; }
        redStoreMaxIdx(mv, mi, redMax, redIdx, lane, wid);
      }
      __syncthreads();
      {
        float m = readMax32(redMax, redIdx, &imax);
        dt = CFLF / (m + EPSF);
      }
      if (it == 5) break;

      float iS1 = 0.f, iS2 = 0.f, iS3 = 0.f, iS4 = 0.f;

      // ---- P2..P5: forward horizon (lazy normalization) ----
      {
        gr[s0] = (1.f - vv[s0]) * 0.125f;
        gr[s1i] = (1.f - vv[s1i]) * 0.125f;
        gup[s0] = 0.f; gup[s1i] = 0.f;
      }
#pragma unroll
      for (int h = 0; h < 4; h++) {
        const float* zi = (h == 0) ? rz : (h == 1 ? z1 : (h == 2 ? z2 : z3));
        float* zo = (h == 0) ? z1 : (h == 1 ? z2 : (h == 2 ? z3 : z4));
        float iS;
        if (h == 0) iS = invR0;
        else {
          float S = readSum32(redS + 32 * (h - 1));
          iS = 1.f / S;
          if (h == 1) iS1 = iS; else if (h == 2) iS2 = iS; else iS3 = iS;
        }
        float rm = zi[smm] * iS, r0 = zi[s0] * iS, r1 = zi[s1i] * iS, rp = zi[sp2] * iS;
        float um = up[smm], u0 = up[s0], u1 = up[s1i];
        float Fm = um > 0.f ? um * rm : um * r0;
        float F0 = u0 > 0.f ? u0 * r0 : u0 * r1;
        float F1 = u1 > 0.f ? u1 * r1 : u1 * rp;
        float y0 = r0 - dt * (F0 - Fm);
        float y1 = r1 - dt * (F1 - F0);
        float o0 = fabsf(y0) + EPSF, o1 = fabsf(y1) + EPSF;
        zo[s0] = o0; zo[s1i] = o1;
        redStoreSum(o0 + o1, redS + 32 * h, lane, wid);
        __syncthreads();
      }

      // ---- backward through the 4 stages ----
      float gdt = 0.f;
#pragma unroll
      for (int h = 3; h >= 0; h--) {
        const float* zi = (h == 0) ? rz : (h == 1 ? z1 : (h == 2 ? z2 : z3));
        const float* zo = (h == 0) ? z1 : (h == 1 ? z2 : (h == 2 ? z3 : z4));
        float iSin = (h == 0) ? invR0 : (h == 1 ? iS1 : (h == 2 ? iS2 : iS3));
        float iSout;
        if (h == 3) { iS4 = 1.f / readSum32(redS + 96); iSout = iS4; }
        else {
          iSout = (h == 0) ? iS1 : (h == 1 ? iS2 : iS3);
          gdt += readSum32(redPart);
        }
        {
          float rm = zi[smm] * iSin, r0 = zi[s0] * iSin, r1 = zi[s1i] * iSin,
                rp = zi[sp2] * iSin;
          float um = up[smm], u0 = up[s0], u1 = up[s1i];
          float Fm = um > 0.f ? um * rm : um * r0;
          float F0 = u0 > 0.f ? u0 * r0 : u0 * r1;
          float F1 = u1 > 0.f ? u1 * r1 : u1 * rp;
          Ft[s0] = F0; Ft[s1i] = F1;
          yb[s0] = r0 - dt * (F0 - Fm);
          yb[s1i] = r1 - dt * (F1 - F0);
          float dp = gr[s0] * zo[s0] * iSout + gr[s1i] * zo[s1i] * iSout;
          redStoreSum(dp, redDot, lane, wid);
        }
        __syncthreads();
        {
          float dotv = readSum32(redDot);
          float gw0 = (gr[s0] - dotv) * iSout;
          float gw1 = (gr[s1i] - dotv) * iSout;
          float y0 = yb[s0], y1 = yb[s1i];
          gy[s0] = y0 > 0.f ? gw0 : (y0 < 0.f ? -gw0 : 0.f);
          gy[s1i] = y1 > 0.f ? gw1 : (y1 < 0.f ? -gw1 : 0.f);
        }
        __syncthreads();
        {
          float gym = gy[smm], gy0 = gy[s0], gy1 = gy[s1i], gyp = gy[sp2];
          float Ftm = Ft[smm], Ft0 = Ft[s0], Ft1 = Ft[s1i];
          float um = up[smm], u0 = up[s0], u1 = up[s1i];
          float r0 = zi[s0] * iSin, r1 = zi[s1i] * iSin, rp = zi[sp2] * iSin;
          float part = gy0 * (Ftm - Ft0) + gy1 * (Ft0 - Ft1);
          float gFs0 = dt * (gy1 - gy0), gFm0 = dt * (gy0 - gym);
          float gFs1 = dt * (gyp - gy1), gFm1 = dt * (gy1 - gy0);
          gup[s0] += gFs0 * (u0 > 0.f ? r0 : r1);
          gup[s1i] += gFs1 * (u1 > 0.f ? r1 : rp);
          gr[s0] = gy0 + (u0 > 0.f ? u0 * gFs0 : 0.f) + (um > 0.f ? 0.f : um * gFm0);
          gr[s1i] = gy1 + (u1 > 0.f ? u1 * gFs1 : 0.f) + (u0 > 0.f ? 0.f : u0 * gFm1);
          redStoreSum(part, redPart, lane, wid);
        }
        __syncthreads();
      }
      // ---- PD: dt/max argmax path ----
      {
        gdt += readSum32(redPart);
        float gm = gdt * (-dt * dt * (1.0f / CFLF));
        if (tid == (imax >> 1)) {
          float uv = up[imax];
          gup[imax] += gm * (uv > 0.f ? 1.f : (uv < 0.f ? -1.f : 0.f));
        }
      }
      __syncthreads();
      // ---- PE: u -= lr * leray(gup)  (adjoint Leray == Leray) ----
      {
        float2 c = conv101(gup, s0);
        u[s0] -= 0.1f * c.x;
        u[s1i] -= 0.1f * c.y;
      }
      __syncthreads();
    }

    // ---- PF2: outer advect with kappa (uses up, dt from it==5 P1) ----
    {
      float kap = (ko == 0) ? 0.01f : ((ko == 1) ? 0.005f : 0.0f);
      float rm = rz[smm] * invR0, r0 = rz[s0] * invR0, r1 = rz[s1i] * invR0,
            rp = rz[sp2] * invR0;
      float um = up[smm], u0 = up[s0], u1 = up[s1i];
      float Fm = um > 0.f ? um * rm : um * r0;
      float F0 = u0 > 0.f ? u0 * r0 : u0 * r1;
      float F1 = u1 > 0.f ? u1 * r1 : u1 * rp;
      float y0 = r0 - dt * (F0 - Fm) + kap * dt * (r1 + rm - 2.f * r0);
      float y1 = r1 - dt * (F1 - F0) + kap * dt * (rp + r0 - 2.f * r1);
      float o0 = fabsf(y0) + EPSF, o1 = fabsf(y1) + EPSF;
      rzo[s0] = o0; rzo[s1i] = o1;
      redStoreSum(o0 + o1, redF, lane, wid);
    }
    __syncthreads();
    { float* t = rz; rz = rzo; rzo = t; }
  }

  // ---- FO: rho_f = (rho + 0.1 v) / sum ----
  float t0, t1;
  {
    float invR = 1.f / readSum32(redF);
    t0 = rz[s0] * invR + 0.1f * vv[s0];
    t1 = rz[s1i] * invR + 0.1f * vv[s1i];
    redStoreSum(t0 + t1, redR, lane, wid);
  }
  __syncthreads();
  {
    float invSf = 1.f / readSum32(redR);
    g_rhof[b * Sn + s0] = t0 * invSf;
    g_rhof[b * Sn + s1i] = t1 * invSf;
  }
}

// ------------------------------------------------------------------
// Kernel C: out = haar_idwt(rho_f[:, :, None] * band_w[BAND_IDX]).
// ------------------------------------------------------------------
__global__ void __launch_bounds__(256) kC(const float* __restrict__ bw,
                                          float* __restrict__ out) {
  int blk = blockIdx.x;
  int b = blk >> 8, k = blk & 255;
  const float* rf = g_rhof + b * Sn;
  float A  = rf[k] * C22;
  float E  = rf[256 + k] * C22;
  float C0 = rf[512 + 2 * k] * 0.5f;
  float C1 = rf[512 + 2 * k + 1] * 0.5f;
  float D0 = rf[1024 + 4 * k] * IR2;
  float D1 = rf[1024 + 4 * k + 1] * IR2;
  float D2 = rf[1024 + 4 * k + 2] * IR2;
  float D3 = rf[1024 + 4 * k + 3] * IR2;

  float s1[8], s2[8], s3[8];
#pragma unroll
  for (int j = 0; j < 8; j++) {
    float Ej = (j < 4) ? E : -E;
    float Cj = (j < 4) ? C0 : C1;
    if ((j & 3) >= 2) Cj = -Cj;
    float Dj = (j >> 1) == 0 ? D0 : ((j >> 1) == 1 ? D1 : ((j >> 1) == 2 ? D2 : D3));
    if (j & 1) Dj = -Dj;
    s1[j] = Ej; s2[j] = Cj; s3[j] = Dj;
  }

  const float4* b0 = (const float4*)bw;
  const float4* b1 = (const float4*)(bw + Dn);
  const float4* b2 = (const float4*)(bw + 2 * Dn);
  const float4* b3 = (const float4*)(bw + 3 * Dn);
  float4* ob = (float4*)(out + ((size_t)b * Sn + (size_t)k * 8) * Dn);

  for (int c = threadIdx.x; c < Dn / 4; c += 256) {
    float4 w0 = b0[c], w1 = b1[c], w2 = b2[c], w3 = b3[c];
#pragma unroll
    for (int j = 0; j < 8; j++) {
      float4 o;
      o.x = A * w0.x + s1[j] * w1.x + s2[j] * w2.x + s3[j] * w3.x;
      o.y = A * w0.y + s1[j] * w1.y + s2[j] * w2.y + s3[j] * w3.y;
      o.z = A * w0.z + s1[j] * w1.z + s2[j] * w2.z + s3[j] * w3.z;
      o.w = A * w0.w + s1[j] * w1.w + s2[j] * w2.w + s3[j] * w3.w;
      __stcs(ob + j * (Dn / 4) + c, o);
    }
  }
}

// ------------------------------------------------------------------
#define SMEMB ((15 * Sn + 512) * 4)

extern "C" void kernel_launch(void* const* d_in, const int* in_sizes, int n_in,
                              void* d_out, int out_size) {
  const float* x   = (const float*)d_in[0];
  const float* w   = (const float*)d_in[1];
  const float* phi = (const float*)d_in[2];
  const float* bw  = (const float*)d_in[3];
  float* out = (float*)d_out;

  cudaFuncSetAttribute((const void*)kB, cudaFuncAttributeMaxDynamicSharedMemorySize, SMEMB);

  kA<<<Bn * 256, 256>>>(x, w);
  kB<<<Bn, 1024, SMEMB>>>(phi);
  kC<<<Bn * 256, 256>>>(bw, out);
}

// round 7
// speedup vs baseline: 1.9573x; 1.3269x over previous
#include <cuda_runtime.h>
#include <math.h>

#define Bn 8
#define Sn 2048
#define Dn 2048
#define SMASK 2047
#define IR2 0.70710678118654752f
#define C22 0.35355339059327379f
#define EPSF 1e-8f
#define CFLF 0.4f
#define SQRTD 45.254833995939045f
#define MW 44

__device__ float g_rho_raw[Bn * Sn];
__device__ float g_pt[Bn * Sn];
__device__ float g_rhof[Bn * Sn];

// ------------------------------------------------------------------
// Compile-time Leray taps L (101) and L^2 taps M (2*MW+1), both exact
// linear equivalents of the reference's 50 Jacobi sweeps + grad/div.
// ------------------------------------------------------------------
struct TapsF { float L[101]; };
struct MTapsF { float M[2 * MW + 1]; };

__host__ __device__ constexpr TapsF makeTapsF() {
  double h[103] = {};
  for (int m = -49; m <= 49; m++) {
    int am = m < 0 ? -m : m;
    double term = 1.0;
    for (int i = 0; i < am; i++) term *= 0.5;
    double acc = 0.0;
    for (int k = am; k <= 49; k += 2) {
      acc += term;
      int j = (k + m) / 2;
      term = term * (double)((k + 1) * (k + 2)) / (4.0 * (double)((j + 1) * (k + 1 - j)));
    }
    h[51 + m] = -0.5 * acc;
  }
  TapsF t{};
  for (int m = -50; m <= 50; m++) {
    double v = 2.0 * h[51 + m] - h[51 + m - 1] - h[51 + m + 1];
    t.L[50 + m] = (float)((m == 0 ? 1.0 : 0.0) + v);
  }
  return t;
}

__host__ __device__ constexpr MTapsF makeM() {
  double h[103] = {};
  for (int m = -49; m <= 49; m++) {
    int am = m < 0 ? -m : m;
    double term = 1.0;
    for (int i = 0; i < am; i++) term *= 0.5;
    double acc = 0.0;
    for (int k = am; k <= 49; k += 2) {
      acc += term;
      int j = (k + m) / 2;
      term = term * (double)((k + 1) * (k + 2)) / (4.0 * (double)((j + 1) * (k + 1 - j)));
    }
    h[51 + m] = -0.5 * acc;
  }
  double L[101] = {};
  for (int m = -50; m <= 50; m++) {
    double v = 2.0 * h[51 + m] - h[51 + m - 1] - h[51 + m + 1];
    L[50 + m] = (m == 0 ? 1.0 : 0.0) + v;
  }
  MTapsF t{};
  for (int m = -MW; m <= MW; m++) {
    double acc = 0.0;
    for (int j = -50; j <= 50; j++) {
      int k = m - j;
      if (k >= -50 && k <= 50) acc += L[50 + j] * L[50 + k];
    }
    t.M[MW + m] = (float)acc;
  }
  return t;
}

__constant__ TapsF TAPS = makeTapsF();
__constant__ MTapsF MT = makeM();

// Leray conv (101 taps) for one output pair (s0, s0+1), s0 even.
__device__ __forceinline__ float2 conv101(const float* __restrict__ in, int s0) {
  float o0 = 0.f, o1 = 0.f;
  const int base = s0 + (Sn - 50);
#pragma unroll
  for (int j = 0; j <= 50; j++) {
    int e = (base + 2 * j) & SMASK;
    float2 w = *(const float2*)(in + e);
    const float tA = TAPS.L[2 * j];
    o0 = fmaf(tA, w.x, o0);
    o1 = fmaf(tA, w.y, o1);
    if (j <= 49) { const float tB = TAPS.L[2 * j + 1]; o0 = fmaf(tB, w.y, o0); }
    if (j >= 1)  { const float tC = TAPS.L[2 * j - 1]; o1 = fmaf(tC, w.x, o1); }
  }
  return make_float2(o0, o1);
}

// L^2 conv (2*MW+1 taps) for one output pair.
__device__ __forceinline__ float2 convM(const float* __restrict__ in, int s0) {
  float o0 = 0.f, o1 = 0.f;
  const int base = s0 + (Sn - MW);
#pragma unroll
  for (int j = 0; j <= MW; j++) {
    int e = (base + 2 * j) & SMASK;
    float2 w = *(const float2*)(in + e);
    const float tA = MT.M[2 * j];
    o0 = fmaf(tA, w.x, o0);
    o1 = fmaf(tA, w.y, o1);
    if (j < MW)  { const float tB = MT.M[2 * j + 1]; o0 = fmaf(tB, w.y, o0); }
    if (j >= 1)  { const float tC = MT.M[2 * j - 1]; o1 = fmaf(tC, w.x, o1); }
  }
  return make_float2(o0, o1);
}

// ------------------------------------------------------------------
// Kernel A: fused rho_raw = ||haar_dwt(x)||_2 over D, and per_token = x.w
// ------------------------------------------------------------------
__global__ void __launch_bounds__(256) kA(const float* __restrict__ x,
                                          const float* __restrict__ w) {
  int blk = blockIdx.x;
  int b = blk >> 8, k = blk & 255;
  const float4* base = (const float4*)(x + ((size_t)b * Sn + (size_t)k * 8) * Dn);
  const float4* w4 = (const float4*)w;

  float acc[16];
#pragma unroll
  for (int q = 0; q < 16; q++) acc[q] = 0.f;

  for (int c = threadIdx.x; c < Dn / 4; c += 256) {
    float4 xr[8];
#pragma unroll
    for (int j = 0; j < 8; j++) xr[j] = __ldcs(base + j * (Dn / 4) + c);
    float4 wv = w4[c];
#pragma unroll
    for (int comp = 0; comp < 4; comp++) {
      float v0 = ((const float*)&xr[0])[comp];
      float v1 = ((const float*)&xr[1])[comp];
      float v2 = ((const float*)&xr[2])[comp];
      float v3 = ((const float*)&xr[3])[comp];
      float v4 = ((const float*)&xr[4])[comp];
      float v5 = ((const float*)&xr[5])[comp];
      float v6 = ((const float*)&xr[6])[comp];
      float v7 = ((const float*)&xr[7])[comp];
      float wc = ((const float*)&wv)[comp];
      float e0 = v0 + v1, e1 = v2 + v3, e2 = v4 + v5, e3 = v6 + v7;
      float d10 = v0 - v1, d11 = v2 - v3, d12 = v4 - v5, d13 = v6 - v7;
      float a20 = e0 + e1, a21 = e2 + e3;
      float d20 = e0 - e1, d21 = e2 - e3;
      float a3 = a20 + a21, d3 = a20 - a21;
      acc[0] += a3 * a3;   acc[1] += d3 * d3;
      acc[2] += d20 * d20; acc[3] += d21 * d21;
      acc[4] += d10 * d10; acc[5] += d11 * d11;
      acc[6] += d12 * d12; acc[7] += d13 * d13;
      acc[8]  += v0 * wc; acc[9]  += v1 * wc; acc[10] += v2 * wc; acc[11] += v3 * wc;
      acc[12] += v4 * wc; acc[13] += v5 * wc; acc[14] += v6 * wc; acc[15] += v7 * wc;
    }
  }

  __shared__ float red[128];
  int lane = threadIdx.x & 31, wid = threadIdx.x >> 5;
#pragma unroll
  for (int q = 0; q < 16; q++) {
    float val = acc[q];
#pragma unroll
    for (int o = 16; o; o >>= 1) val += __shfl_xor_sync(0xffffffffu, val, o);
    if (lane == 0) red[q * 8 + wid] = val;
  }
  __syncthreads();
  if (threadIdx.x < 16) {
    float s2 = 0.f;
#pragma unroll
    for (int ww = 0; ww < 8; ww++) s2 += red[threadIdx.x * 8 + ww];
    int bs = b * Sn;
    int t = threadIdx.x;
    if (t == 0)      g_rho_raw[bs + k]                      = sqrtf(s2) * C22;
    else if (t == 1) g_rho_raw[bs + 256 + k]                = sqrtf(s2) * C22;
    else if (t < 4)  g_rho_raw[bs + 512 + 2 * k + (t - 2)]  = sqrtf(s2) * 0.5f;
    else if (t < 8)  g_rho_raw[bs + 1024 + 4 * k + (t - 4)] = sqrtf(s2) * IR2;
    else             g_pt[bs + 8 * k + (t - 8)] = s2;
  }
}

// ------------------------------------------------------------------
// One-sync reductions.
// ------------------------------------------------------------------
__device__ __forceinline__ void redStoreSum(float v, float* buf, int lane, int wid) {
#pragma unroll
  for (int o = 16; o; o >>= 1) v += __shfl_xor_sync(0xffffffffu, v, o);
  if (lane == 0) buf[wid] = v;
}
__device__ __forceinline__ float readSum32(const float* buf) {
  float s0 = 0.f, s1 = 0.f, s2 = 0.f, s3 = 0.f;
#pragma unroll
  for (int i = 0; i < 8; i++) {
    s0 += buf[4 * i]; s1 += buf[4 * i + 1]; s2 += buf[4 * i + 2]; s3 += buf[4 * i + 3];
  }
  return (s0 + s1) + (s2 + s3);
}
__device__ __forceinline__ void redStoreMaxIdx(float v, int idx, float* bv, int* bi,
                                               int lane, int wid) {
#pragma unroll
  for (int o = 16; o; o >>= 1) {
    float ov = __shfl_xor_sync(0xffffffffu, v, o);
    int oi = __shfl_xor_sync(0xffffffffu, idx, o);
    if (ov > v || (ov == v && oi < idx)) { v = ov; idx = oi; }
  }
  if (lane == 0) { bv[wid] = v; bi[wid] = idx; }
}
__device__ __forceinline__ float readMax32(const float* bv, const int* bi, int* oi) {
  float m = -1e30f; int mi = 1 << 30;
#pragma unroll
  for (int i = 0; i < 32; i++) {
    float v = bv[i]; int ii = bi[i];
    if (v > m || (v == m && ii < mi)) { m = v; mi = ii; }
  }
  *oi = mi;
  return m;
}

// ------------------------------------------------------------------
// Kernel B: full pipeline, one block/batch, 1024 threads, pair layout.
// up-iteration uses M = L^2; u never materialized. Backward = 1 phase/stage.
// ------------------------------------------------------------------
__global__ void __launch_bounds__(1024, 1) kB(const float* __restrict__ phi_g) {
  int b = blockIdx.x;
  extern __shared__ float sm[];
  float* phi_s = sm + 0 * Sn;
  float* vv   = sm + 1 * Sn;
  float* rb0  = sm + 2 * Sn;
  float* rb1  = sm + 3 * Sn;
  float* up0  = sm + 4 * Sn;
  float* upA  = sm + 5 * Sn;
  float* upB  = sm + 6 * Sn;
  float* z1   = sm + 7 * Sn;
  float* z2   = sm + 8 * Sn;
  float* z3   = sm + 9 * Sn;
  float* z4   = sm + 10 * Sn;
  float* Ft0a = sm + 11 * Sn;
  float* Ft1a = sm + 12 * Sn;
  float* Ft2a = sm + 13 * Sn;
  float* Ft3a = sm + 14 * Sn;
  float* grA  = sm + 15 * Sn;
  float* grB  = sm + 16 * Sn;
  float* gup  = sm + 17 * Sn;
  float* red  = sm + 18 * Sn;
  float* redMax = red;
  int*   redIdx = (int*)(red + 32);
  float* redSS  = red + 64;            // 4 x 32
  float* dotB0  = red + 192;
  float* dotB1  = red + 224;
  float* redPart = red + 256;
  float* redR   = red + 288;
  float* redF   = red + 320;

  const int tid = threadIdx.x;
  const int lane = tid & 31, wid = tid >> 5;
  const int s0 = 2 * tid, s1i = s0 + 1;
  const int smm = (s0 + SMASK) & SMASK;
  const int sp2 = (s0 + 2) & SMASK;

  // ---- I1 ----
#pragma unroll
  for (int e = 0; e < 2; e++) {
    int s = tid + (e << 10);
    phi_s[s] = phi_g[s];
    rb0[s] = g_rho_raw[b * Sn + s] + EPSF;
  }
  if (tid < 256) {
    const float* p = g_pt + b * Sn + tid * 8;
    float v0 = p[0], v1 = p[1], v2 = p[2], v3 = p[3];
    float v4 = p[4], v5 = p[5], v6 = p[6], v7 = p[7];
    float e0 = v0 + v1, e1 = v2 + v3, e2 = v4 + v5, e3 = v6 + v7;
    float d10 = v0 - v1, d11 = v2 - v3, d12 = v4 - v5, d13 = v6 - v7;
    float a20 = e0 + e1, a21 = e2 + e3;
    float d20 = e0 - e1, d21 = e2 - e3;
    float a3 = a20 + a21, d3 = a20 - a21;
    vv[tid]               = fabsf(a3) * C22 * SQRTD;
    vv[256 + tid]         = fabsf(d3) * C22 * SQRTD;
    vv[512 + 2 * tid]     = fabsf(d20) * 0.5f * SQRTD;
    vv[512 + 2 * tid + 1] = fabsf(d21) * 0.5f * SQRTD;
    vv[1024 + 4 * tid]     = fabsf(d10) * IR2 * SQRTD;
    vv[1024 + 4 * tid + 1] = fabsf(d11) * IR2 * SQRTD;
    vv[1024 + 4 * tid + 2] = fabsf(d12) * IR2 * SQRTD;
    vv[1024 + 4 * tid + 3] = fabsf(d13) * IR2 * SQRTD;
  }
  __syncthreads();
  // ---- I2 ----
  redStoreSum(rb0[s0] + rb0[s1i], redF, lane, wid);
  redStoreSum((vv[s0] + EPSF) + (vv[s1i] + EPSF), redR, lane, wid);
  __syncthreads();
  // ---- I3: normalize v ----
  {
    float inv = 1.f / readSum32(redR);
    vv[s0] = (vv[s0] + EPSF) * inv;
    vv[s1i] = (vv[s1i] + EPSF) * inv;
  }
  __syncthreads();
  // ---- I4a: gup = grad1(v) ----
  gup[s0] = vv[s1i] - vv[s0];
  gup[s1i] = vv[sp2] - vv[s1i];
  __syncthreads();
  // ---- I4b: up0 = L * grad1(v) ; max ----
  {
    float2 c = conv101(gup, s0);
    up0[s0] = c.x; up0[s1i] = c.y;
    float a0 = fabsf(c.x), a1 = fabsf(c.y);
    float mv; int mi;
    if (a0 >= a1) { mv = a0; mi = s0; } else { mv = a1; mi = s1i; }
    redStoreMaxIdx(mv, mi, redMax, redIdx, lane, wid);
  }
  __syncthreads();

  float dt0 = 0.f; int imax0 = 0;
  float invRho = 0.f;
  float* rz = rb0;
  float* rzo = rb1;

  for (int ko = 0; ko < 3; ko++) {
    // ---- PR1: reaction ----
    {
      if (ko == 0) {
        int mi; float m = readMax32(redMax, redIdx, &mi);
        dt0 = CFLF / (m + EPSF); imax0 = mi;
      }
      float invR = 1.f / readSum32(redF);
      float rv0 = rz[s0] * invR, rv1 = rz[s1i] * invR;
      float w0 = rv0 * expf(-0.1f * (phi_s[s0] + logf(rv0))) + EPSF;
      float w1 = rv1 * expf(-0.1f * (phi_s[s1i] + logf(rv1))) + EPSF;
      rz[s0] = w0; rz[s1i] = w1;
      redStoreSum(w0 + w1, redR, lane, wid);
    }
    __syncthreads();

    float dt = 0.f; int imax = 0;
    float sOut[4] = {0.f, 0.f, 0.f, 0.f};

    for (int it = 0; it < 5; it++) {
      const float* uin = (it == 0) ? up0 : ((it & 1) ? upB : upA);
      float* uout = (it & 1) ? upA : upB;
      float part = 0.f;

      // ---- F0 ----
      {
        if (it == 0) { invRho = 1.f / readSum32(redR); dt = dt0; imax = imax0; }
        else { float m = readMax32(redMax, redIdx, &imax); dt = CFLF / (m + EPSF); }
        gup[s0] = 0.f; gup[s1i] = 0.f;
        float rm = rz[smm] * invRho, r0 = rz[s0] * invRho,
              r1 = rz[s1i] * invRho, rp = rz[sp2] * invRho;
        float um = uin[smm], u0 = uin[s0], u1 = uin[s1i];
        float Fm = um > 0.f ? um * rm : um * r0;
        float F0 = u0 > 0.f ? u0 * r0 : u0 * r1;
        float F1 = u1 > 0.f ? u1 * r1 : u1 * rp;
        float y0 = r0 - dt * (F0 - Fm), y1 = r1 - dt * (F1 - F0);
        z1[s0] = y0; z1[s1i] = y1;
        Ft0a[s0] = F0; Ft0a[s1i] = F1;
        redStoreSum((fabsf(y0) + EPSF) + (fabsf(y1) + EPSF), redSS, lane, wid);
      }
      __syncthreads();

      // ---- F1..F3 ----
#pragma unroll
      for (int h = 1; h < 4; h++) {
        const float* zi = (h == 1) ? z1 : (h == 2 ? z2 : z3);
        float* zo = (h == 1) ? z2 : (h == 2 ? z3 : z4);
        float* Fta = (h == 1) ? Ft1a : (h == 2 ? Ft2a : Ft3a);
        float iS = 1.f / readSum32(redSS + 32 * (h - 1));
        sOut[h - 1] = iS;
        float rm = (fabsf(zi[smm]) + EPSF) * iS, r0 = (fabsf(zi[s0]) + EPSF) * iS,
              r1 = (fabsf(zi[s1i]) + EPSF) * iS, rp = (fabsf(zi[sp2]) + EPSF) * iS;
        float um = uin[smm], u0 = uin[s0], u1 = uin[s1i];
        float Fm = um > 0.f ? um * rm : um * r0;
        float F0 = u0 > 0.f ? u0 * r0 : u0 * r1;
        float F1 = u1 > 0.f ? u1 * r1 : u1 * rp;
        float y0 = r0 - dt * (F0 - Fm), y1 = r1 - dt * (F1 - F0);
        zo[s0] = y0; zo[s1i] = y1;
        Fta[s0] = F0; Fta[s1i] = F1;
        float o0 = fabsf(y0) + EPSF, o1 = fabsf(y1) + EPSF;
        redStoreSum(o0 + o1, redSS + 32 * h, lane, wid);
        if (h == 3) {
          float dp = (1.f - vv[s0]) * 0.125f * o0 + (1.f - vv[s1i]) * 0.125f * o1;
          redStoreSum(dp, dotB1, lane, wid);
        }
        __syncthreads();
      }

      // ---- G3..G0: one phase per backward stage ----
#pragma unroll
      for (int h = 3; h >= 0; h--) {
        const float* zout = (h == 3) ? z4 : (h == 2 ? z3 : (h == 1 ? z2 : z1));
        const float* zin  = (h == 3) ? z3 : (h == 2 ? z2 : (h == 1 ? z1 : rz));
        const float* Fta  = (h == 3) ? Ft3a : (h == 2 ? Ft2a : (h == 1 ? Ft1a : Ft0a));
        const float* grOld = (((h + 1) & 1) ? grB : grA);   // grNew(h+1)
        float* grNew = ((h & 1) ? grB : grA);
        const float* dotRd = ((h & 1) ? dotB1 : dotB0);
        float* dotWr = ((h & 1) ? dotB0 : dotB1);

        if (h == 3) sOut[3] = 1.f / readSum32(redSS + 96);
        float iSout = sOut[h];
        float iSin = (h == 0) ? invRho : sOut[h - 1];
        float dotv = readSum32(dotRd) * iSout;

        // gy at 4 positions (local recompute)
        int idx4[4] = {smm, s0, s1i, sp2};
        float gy4[4];
#pragma unroll
        for (int q = 0; q < 4; q++) {
          int t = idx4[q];
          float yv = zout[t];
          float gin = (h == 3) ? (1.f - vv[t]) * 0.125f : grOld[t];
          float gw = (gin - dotv) * iSout;
          gy4[q] = yv > 0.f ? gw : (yv < 0.f ? -gw : 0.f);
        }
        float gym = gy4[0], gy0 = gy4[1], gy1 = gy4[2], gyp = gy4[3];

        float zi0 = zin[s0], zi1 = zin[s1i], zip = zin[sp2];
        float o0, o1, r0, r1, rp;
        if (h == 0) {
          o0 = zi0; o1 = zi1;
          r0 = zi0 * iSin; r1 = zi1 * iSin; rp = zip * iSin;
        } else {
          o0 = fabsf(zi0) + EPSF; o1 = fabsf(zi1) + EPSF;
          r0 = o0 * iSin; r1 = o1 * iSin; rp = (fabsf(zip) + EPSF) * iSin;
        }
        float um = uin[smm], u0 = uin[s0], u1 = uin[s1i];
        float Ftm = Fta[smm], Ftv0 = Fta[s0], Ftv1 = Fta[s1i];
        part += gy0 * (Ftm - Ftv0) + gy1 * (Ftv0 - Ftv1);
        float gFs0 = dt * (gy1 - gy0), gFm0 = dt * (gy0 - gym), gFs1 = dt * (gyp - gy1);
        gup[s0]  += gFs0 * (u0 > 0.f ? r0 : r1);
        gup[s1i] += gFs1 * (u1 > 0.f ? r1 : rp);
        if (h > 0) {
          float ngr0 = gy0 + (u0 > 0.f ? u0 * gFs0 : 0.f) + (um > 0.f ? 0.f : um * gFm0);
          float ngr1 = gy1 + (u1 > 0.f ? u1 * gFs1 : 0.f) + (u0 > 0.f ? 0.f : u0 * gFs0);
          grNew[s0] = ngr0; grNew[s1i] = ngr1;
          redStoreSum(ngr0 * o0 + ngr1 * o1, dotWr, lane, wid);
        } else {
          redStoreSum(part, redPart, lane, wid);
        }
        __syncthreads();
      }

      // ---- PE': up_{n+1} = up_n - 0.1*M*(gup + argmax corr); max ----
      {
        float gdt = readSum32(redPart);
        float gm = gdt * (-dt * dt * (1.0f / CFLF));
        float uv = uin[imax];
        float sg = uv > 0.f ? 1.f : (uv < 0.f ? -1.f : 0.f);
        float2 c = convM(gup, s0);
        int dd0 = ((imax - s0 + 1024) & SMASK) - 1024;
        int dd1 = ((imax - s1i + 1024) & SMASK) - 1024;
        float corr0 = (dd0 >= -MW && dd0 <= MW) ? gm * sg * MT.M[MW + dd0] : 0.f;
        float corr1 = (dd1 >= -MW && dd1 <= MW) ? gm * sg * MT.M[MW + dd1] : 0.f;
        float n0 = uin[s0] - 0.1f * (c.x + corr0);
        float n1 = uin[s1i] - 0.1f * (c.y + corr1);
        uout[s0] = n0; uout[s1i] = n1;
        float a0 = fabsf(n0), a1 = fabsf(n1);
        float mv; int mi;
        if (a0 >= a1) { mv = a0; mi = s0; } else { mv = a1; mi = s1i; }
        redStoreMaxIdx(mv, mi, redMax, redIdx, lane, wid);
      }
      __syncthreads();
    }

    // ---- PF2: outer advect (up_5 = upB, dt from its max) ----
    {
      int mi; float m = readMax32(redMax, redIdx, &mi);
      float dtf = CFLF / (m + EPSF);
      float kap = (ko == 0) ? 0.01f : ((ko == 1) ? 0.005f : 0.0f);
      const float* uf = upB;
      float rm = rz[smm] * invRho, r0 = rz[s0] * invRho,
            r1 = rz[s1i] * invRho, rp = rz[sp2] * invRho;
      float um = uf[smm], u0 = uf[s0], u1 = uf[s1i];
      float Fm = um > 0.f ? um * rm : um * r0;
      float F0 = u0 > 0.f ? u0 * r0 : u0 * r1;
      float F1 = u1 > 0.f ? u1 * r1 : u1 * rp;
      float y0 = r0 - dtf * (F0 - Fm) + kap * dtf * (r1 + rm - 2.f * r0);
      float y1 = r1 - dtf * (F1 - F0) + kap * dtf * (rp + r0 - 2.f * r1);
      float o0 = fabsf(y0) + EPSF, o1 = fabsf(y1) + EPSF;
      rzo[s0] = o0; rzo[s1i] = o1;
      redStoreSum(o0 + o1, redF, lane, wid);
    }
    __syncthreads();
    { float* t = rz; rz = rzo; rzo = t; }
  }

  // ---- FO ----
  float t0, t1;
  {
    float invR = 1.f / readSum32(redF);
    t0 = rz[s0] * invR + 0.1f * vv[s0];
    t1 = rz[s1i] * invR + 0.1f * vv[s1i];
    redStoreSum(t0 + t1, redR, lane, wid);
  }
  __syncthreads();
  {
    float invSf = 1.f / readSum32(redR);
    g_rhof[b * Sn + s0] = t0 * invSf;
    g_rhof[b * Sn + s1i] = t1 * invSf;
  }
}

// ------------------------------------------------------------------
// Kernel C: out = haar_idwt(rho_f[:, :, None] * band_w[BAND_IDX]).
// ------------------------------------------------------------------
__global__ void __launch_bounds__(256) kC(const float* __restrict__ bw,
                                          float* __restrict__ out) {
  int blk = blockIdx.x;
  int b = blk >> 8, k = blk & 255;
  const float* rf = g_rhof + b * Sn;
  float A  = rf[k] * C22;
  float E  = rf[256 + k] * C22;
  float C0 = rf[512 + 2 * k] * 0.5f;
  float C1 = rf[512 + 2 * k + 1] * 0.5f;
  float D0 = rf[1024 + 4 * k] * IR2;
  float D1 = rf[1024 + 4 * k + 1] * IR2;
  float D2 = rf[1024 + 4 * k + 2] * IR2;
  float D3 = rf[1024 + 4 * k + 3] * IR2;

  float s1[8], s2[8], s3[8];
#pragma unroll
  for (int j = 0; j < 8; j++) {
    float Ej = (j < 4) ? E : -E;
    float Cj = (j < 4) ? C0 : C1;
    if ((j & 3) >= 2) Cj = -Cj;
    float Dj = (j >> 1) == 0 ? D0 : ((j >> 1) == 1 ? D1 : ((j >> 1) == 2 ? D2 : D3));
    if (j & 1) Dj = -Dj;
    s1[j] = Ej; s2[j] = Cj; s3[j] = Dj;
  }

  const float4* b0 = (const float4*)bw;
  const float4* b1 = (const float4*)(bw + Dn);
  const float4* b2 = (const float4*)(bw + 2 * Dn);
  const float4* b3 = (const float4*)(bw + 3 * Dn);
  float4* ob = (float4*)(out + ((size_t)b * Sn + (size_t)k * 8) * Dn);

  for (int c = threadIdx.x; c < Dn / 4; c += 256) {
    float4 w0 = b0[c], w1 = b1[c], w2 = b2[c], w3 = b3[c];
#pragma unroll
    for (int j = 0; j < 8; j++) {
      float4 o;
      o.x = A * w0.x + s1[j] * w1.x + s2[j] * w2.x + s3[j] * w3.x;
      o.y = A * w0.y + s1[j] * w1.y + s2[j] * w2.y + s3[j] * w3.y;
      o.z = A * w0.z + s1[j] * w1.z + s2[j] * w2.z + s3[j] * w3.z;
      o.w = A * w0.w + s1[j] * w1.w + s2[j] * w2.w + s3[j] * w3.w;
      __stcs(ob + j * (Dn / 4) + c, o);
    }
  }
}

// ------------------------------------------------------------------
#define SMEMB ((18 * Sn + 512) * 4)

extern "C" void kernel_launch(void* const* d_in, const int* in_sizes, int n_in,
                              void* d_out, int out_size) {
  const float* x   = (const float*)d_in[0];
  const float* w   = (const float*)d_in[1];
  const float* phi = (const float*)d_in[2];
  const float* bw  = (const float*)d_in[3];
  float* out = (float*)d_out;

  cudaFuncSetAttribute((const void*)kB, cudaFuncAttributeMaxDynamicSharedMemorySize, SMEMB);

  kA<<<Bn * 256, 256>>>(x, w);
  kB<<<Bn, 1024, SMEMB>>>(phi);
  kC<<<Bn * 256, 256>>>(bw, out);
}

// round 8
// speedup vs baseline: 2.5606x; 1.3082x over previous
#include <cuda_runtime.h>
#include <math.h>

#define Bn 8
#define Sn 2048
#define Dn 2048
#define SMASK 2047
#define IR2 0.70710678118654752f
#define C22 0.35355339059327379f
#define EPSF 1e-8f
#define CFLF 0.4f
#define SQRTD 45.254833995939045f
#define MW 44

__device__ float g_rho_raw[Bn * Sn];
__device__ float g_pt[Bn * Sn];
__device__ float g_rhof[Bn * Sn];

// ------------------------------------------------------------------
// Compile-time Leray taps L (101) and L^2 taps M (2*MW+1).
// ------------------------------------------------------------------
struct TapsF { float L[101]; };
struct MTapsF { float M[2 * MW + 1]; };

__host__ __device__ constexpr TapsF makeTapsF() {
  double h[103] = {};
  for (int m = -49; m <= 49; m++) {
    int am = m < 0 ? -m : m;
    double term = 1.0;
    for (int i = 0; i < am; i++) term *= 0.5;
    double acc = 0.0;
    for (int k = am; k <= 49; k += 2) {
      acc += term;
      int j = (k + m) / 2;
      term = term * (double)((k + 1) * (k + 2)) / (4.0 * (double)((j + 1) * (k + 1 - j)));
    }
    h[51 + m] = -0.5 * acc;
  }
  TapsF t{};
  for (int m = -50; m <= 50; m++) {
    double v = 2.0 * h[51 + m] - h[51 + m - 1] - h[51 + m + 1];
    t.L[50 + m] = (float)((m == 0 ? 1.0 : 0.0) + v);
  }
  return t;
}

__host__ __device__ constexpr MTapsF makeM() {
  double h[103] = {};
  for (int m = -49; m <= 49; m++) {
    int am = m < 0 ? -m : m;
    double term = 1.0;
    for (int i = 0; i < am; i++) term *= 0.5;
    double acc = 0.0;
    for (int k = am; k <= 49; k += 2) {
      acc += term;
      int j = (k + m) / 2;
      term = term * (double)((k + 1) * (k + 2)) / (4.0 * (double)((j + 1) * (k + 1 - j)));
    }
    h[51 + m] = -0.5 * acc;
  }
  double L[101] = {};
  for (int m = -50; m <= 50; m++) {
    double v = 2.0 * h[51 + m] - h[51 + m - 1] - h[51 + m + 1];
    L[50 + m] = (m == 0 ? 1.0 : 0.0) + v;
  }
  MTapsF t{};
  for (int m = -MW; m <= MW; m++) {
    double acc = 0.0;
    for (int j = -50; j <= 50; j++) {
      int k = m - j;
      if (k >= -50 && k <= 50) acc += L[50 + j] * L[50 + k];
    }
    t.M[MW + m] = (float)acc;
  }
  return t;
}

__constant__ TapsF TAPS = makeTapsF();
__constant__ MTapsF MT = makeM();

__device__ __forceinline__ float2 conv101(const float* __restrict__ in, int s0) {
  float o0 = 0.f, o1 = 0.f;
  const int base = s0 + (Sn - 50);
#pragma unroll
  for (int j = 0; j <= 50; j++) {
    int e = (base + 2 * j) & SMASK;
    float2 w = *(const float2*)(in + e);
    const float tA = TAPS.L[2 * j];
    o0 = fmaf(tA, w.x, o0);
    o1 = fmaf(tA, w.y, o1);
    if (j <= 49) { const float tB = TAPS.L[2 * j + 1]; o0 = fmaf(tB, w.y, o0); }
    if (j >= 1)  { const float tC = TAPS.L[2 * j - 1]; o1 = fmaf(tC, w.x, o1); }
  }
  return make_float2(o0, o1);
}

__device__ __forceinline__ float2 convM(const float* __restrict__ in, int s0) {
  float o0 = 0.f, o1 = 0.f;
  const int base = s0 + (Sn - MW);
#pragma unroll
  for (int j = 0; j <= MW; j++) {
    int e = (base + 2 * j) & SMASK;
    float2 w = *(const float2*)(in + e);
    const float tA = MT.M[2 * j];
    o0 = fmaf(tA, w.x, o0);
    o1 = fmaf(tA, w.y, o1);
    if (j < MW)  { const float tB = MT.M[2 * j + 1]; o0 = fmaf(tB, w.y, o0); }
    if (j >= 1)  { const float tC = MT.M[2 * j - 1]; o1 = fmaf(tC, w.x, o1); }
  }
  return make_float2(o0, o1);
}

// ------------------------------------------------------------------
// Kernel A (unchanged)
// ------------------------------------------------------------------
__global__ void __launch_bounds__(256) kA(const float* __restrict__ x,
                                          const float* __restrict__ w) {
  int blk = blockIdx.x;
  int b = blk >> 8, k = blk & 255;
  const float4* base = (const float4*)(x + ((size_t)b * Sn + (size_t)k * 8) * Dn);
  const float4* w4 = (const float4*)w;

  float acc[16];
#pragma unroll
  for (int q = 0; q < 16; q++) acc[q] = 0.f;

  for (int c = threadIdx.x; c < Dn / 4; c += 256) {
    float4 xr[8];
#pragma unroll
    for (int j = 0; j < 8; j++) xr[j] = __ldcs(base + j * (Dn / 4) + c);
    float4 wv = w4[c];
#pragma unroll
    for (int comp = 0; comp < 4; comp++) {
      float v0 = ((const float*)&xr[0])[comp];
      float v1 = ((const float*)&xr[1])[comp];
      float v2 = ((const float*)&xr[2])[comp];
      float v3 = ((const float*)&xr[3])[comp];
      float v4 = ((const float*)&xr[4])[comp];
      float v5 = ((const float*)&xr[5])[comp];
      float v6 = ((const float*)&xr[6])[comp];
      float v7 = ((const float*)&xr[7])[comp];
      float wc = ((const float*)&wv)[comp];
      float e0 = v0 + v1, e1 = v2 + v3, e2 = v4 + v5, e3 = v6 + v7;
      float d10 = v0 - v1, d11 = v2 - v3, d12 = v4 - v5, d13 = v6 - v7;
      float a20 = e0 + e1, a21 = e2 + e3;
      float d20 = e0 - e1, d21 = e2 - e3;
      float a3 = a20 + a21, d3 = a20 - a21;
      acc[0] += a3 * a3;   acc[1] += d3 * d3;
      acc[2] += d20 * d20; acc[3] += d21 * d21;
      acc[4] += d10 * d10; acc[5] += d11 * d11;
      acc[6] += d12 * d12; acc[7] += d13 * d13;
      acc[8]  += v0 * wc; acc[9]  += v1 * wc; acc[10] += v2 * wc; acc[11] += v3 * wc;
      acc[12] += v4 * wc; acc[13] += v5 * wc; acc[14] += v6 * wc; acc[15] += v7 * wc;
    }
  }

  __shared__ float red[128];
  int lane = threadIdx.x & 31, wid = threadIdx.x >> 5;
#pragma unroll
  for (int q = 0; q < 16; q++) {
    float val = acc[q];
#pragma unroll
    for (int o = 16; o; o >>= 1) val += __shfl_xor_sync(0xffffffffu, val, o);
    if (lane == 0) red[q * 8 + wid] = val;
  }
  __syncthreads();
  if (threadIdx.x < 16) {
    float s2 = 0.f;
#pragma unroll
    for (int ww = 0; ww < 8; ww++) s2 += red[threadIdx.x * 8 + ww];
    int bs = b * Sn;
    int t = threadIdx.x;
    if (t == 0)      g_rho_raw[bs + k]                      = sqrtf(s2) * C22;
    else if (t == 1) g_rho_raw[bs + 256 + k]                = sqrtf(s2) * C22;
    else if (t < 4)  g_rho_raw[bs + 512 + 2 * k + (t - 2)]  = sqrtf(s2) * 0.5f;
    else if (t < 8)  g_rho_raw[bs + 1024 + 4 * k + (t - 4)] = sqrtf(s2) * IR2;
    else             g_pt[bs + 8 * k + (t - 8)] = s2;
  }
}

// ------------------------------------------------------------------
// Reductions: store 32 warp partials; read back with ONE lane-indexed
// LDS + 5 shfl per warp (no 32-LDS broadcast scans).
// ------------------------------------------------------------------
__device__ __forceinline__ void redStoreSum(float v, float* buf, int lane, int wid) {
#pragma unroll
  for (int o = 16; o; o >>= 1) v += __shfl_xor_sync(0xffffffffu, v, o);
  if (lane == 0) buf[wid] = v;
}
__device__ __forceinline__ float readSum32(const float* buf, int lane) {
  float v = buf[lane];
#pragma unroll
  for (int o = 16; o; o >>= 1) v += __shfl_xor_sync(0xffffffffu, v, o);
  return v;
}
__device__ __forceinline__ void redStoreMaxIdx(float v, int idx, float* bv, int* bi,
                                               int lane, int wid) {
#pragma unroll
  for (int o = 16; o; o >>= 1) {
    float ov = __shfl_xor_sync(0xffffffffu, v, o);
    int oi = __shfl_xor_sync(0xffffffffu, idx, o);
    if (ov > v || (ov == v && oi < idx)) { v = ov; idx = oi; }
  }
  if (lane == 0) { bv[wid] = v; bi[wid] = idx; }
}
__device__ __forceinline__ float readMax32(const float* bv, const int* bi, int lane,
                                           int* oi) {
  float v = bv[lane]; int idx = bi[lane];
#pragma unroll
  for (int o = 16; o; o >>= 1) {
    float ov = __shfl_xor_sync(0xffffffffu, v, o);
    int oi2 = __shfl_xor_sync(0xffffffffu, idx, o);
    if (ov > v || (ov == v && oi2 < idx)) { v = ov; idx = oi2; }
  }
  *oi = idx;
  return v;
}

// ------------------------------------------------------------------
// Kernel B
// ------------------------------------------------------------------
__global__ void __launch_bounds__(1024, 1) kB(const float* __restrict__ phi_g) {
  int b = blockIdx.x;
  extern __shared__ float sm[];
  float* phi_s = sm + 0 * Sn;
  float* vv   = sm + 1 * Sn;
  float* rb0  = sm + 2 * Sn;
  float* rb1  = sm + 3 * Sn;
  float* up0  = sm + 4 * Sn;
  float* upA  = sm + 5 * Sn;
  float* upB  = sm + 6 * Sn;
  float* z1   = sm + 7 * Sn;
  float* z2   = sm + 8 * Sn;
  float* z3   = sm + 9 * Sn;
  float* z4   = sm + 10 * Sn;
  float* Ft0a = sm + 11 * Sn;
  float* Ft1a = sm + 12 * Sn;
  float* Ft2a = sm + 13 * Sn;
  float* Ft3a = sm + 14 * Sn;
  float* grA  = sm + 15 * Sn;
  float* grB  = sm + 16 * Sn;
  float* gup  = sm + 17 * Sn;
  float* red  = sm + 18 * Sn;
  float* redMax = red;
  int*   redIdx = (int*)(red + 32);
  float* redSS  = red + 64;            // 4 x 32
  float* dotB0  = red + 192;
  float* dotB1  = red + 224;
  float* redPart = red + 256;
  float* redR   = red + 288;
  float* redF   = red + 320;

  const int tid = threadIdx.x;
  const int lane = tid & 31, wid = tid >> 5;
  const int s0 = 2 * tid, s1i = s0 + 1;
  const int smm = (s0 + SMASK) & SMASK;
  const int sp2 = (s0 + 2) & SMASK;

  // ---- I1 ----
#pragma unroll
  for (int e = 0; e < 2; e++) {
    int s = tid + (e << 10);
    phi_s[s] = phi_g[s];
    rb0[s] = g_rho_raw[b * Sn + s] + EPSF;
  }
  if (tid < 256) {
    const float* p = g_pt + b * Sn + tid * 8;
    float v0 = p[0], v1 = p[1], v2 = p[2], v3 = p[3];
    float v4 = p[4], v5 = p[5], v6 = p[6], v7 = p[7];
    float e0 = v0 + v1, e1 = v2 + v3, e2 = v4 + v5, e3 = v6 + v7;
    float d10 = v0 - v1, d11 = v2 - v3, d12 = v4 - v5, d13 = v6 - v7;
    float a20 = e0 + e1, a21 = e2 + e3;
    float d20 = e0 - e1, d21 = e2 - e3;
    float a3 = a20 + a21, d3 = a20 - a21;
    vv[tid]               = fabsf(a3) * C22 * SQRTD;
    vv[256 + tid]         = fabsf(d3) * C22 * SQRTD;
    vv[512 + 2 * tid]     = fabsf(d20) * 0.5f * SQRTD;
    vv[512 + 2 * tid + 1] = fabsf(d21) * 0.5f * SQRTD;
    vv[1024 + 4 * tid]     = fabsf(d10) * IR2 * SQRTD;
    vv[1024 + 4 * tid + 1] = fabsf(d11) * IR2 * SQRTD;
    vv[1024 + 4 * tid + 2] = fabsf(d12) * IR2 * SQRTD;
    vv[1024 + 4 * tid + 3] = fabsf(d13) * IR2 * SQRTD;
  }
  __syncthreads();
  // ---- I2: raw neighbor reads + partial sums ----
  float raw0 = vv[s0], raw1 = vv[s1i], rawp = vv[sp2];
  redStoreSum(rb0[s0] + rb0[s1i], redF, lane, wid);
  redStoreSum((raw0 + EPSF) + (raw1 + EPSF), redR, lane, wid);
  __syncthreads();
  // ---- I3: normalize v, write gup = grad1(v_norm) ----
  float vvs0, vvs1, sd0, sd1;
  {
    float inv = 1.f / readSum32(redR, lane);
    vvs0 = (raw0 + EPSF) * inv;
    vvs1 = (raw1 + EPSF) * inv;
    vv[s0] = vvs0; vv[s1i] = vvs1;
    sd0 = (1.f - vvs0) * 0.125f;
    sd1 = (1.f - vvs1) * 0.125f;
    gup[s0] = (raw1 - raw0) * inv;
    gup[s1i] = (rawp - raw1) * inv;
  }
  __syncthreads();
  // ---- I4b: up0 = L * grad1(v); max ----
  {
    float2 c = conv101(gup, s0);
    up0[s0] = c.x; up0[s1i] = c.y;
    float a0 = fabsf(c.x), a1 = fabsf(c.y);
    float mv; int mi;
    if (a0 >= a1) { mv = a0; mi = s0; } else { mv = a1; mi = s1i; }
    redStoreMaxIdx(mv, mi, redMax, redIdx, lane, wid);
  }
  __syncthreads();

  float dt0 = 0.f; int imax0 = 0;
  float invRho = 0.f;
  float* rz = rb0;
  float* rzo = rb1;

  for (int ko = 0; ko < 3; ko++) {
    // ---- PR1: reaction ----
    {
      if (ko == 0) {
        int mi; float m = readMax32(redMax, redIdx, lane, &mi);
        dt0 = CFLF / (m + EPSF); imax0 = mi;
      }
      float invR = 1.f / readSum32(redF, lane);
      float rv0 = rz[s0] * invR, rv1 = rz[s1i] * invR;
      float w0 = rv0 * expf(-0.1f * (phi_s[s0] + logf(rv0))) + EPSF;
      float w1 = rv1 * expf(-0.1f * (phi_s[s1i] + logf(rv1))) + EPSF;
      rz[s0] = w0; rz[s1i] = w1;
      redStoreSum(w0 + w1, redR, lane, wid);
    }
    __syncthreads();

    float dt = 0.f; int imax = 0;
    float sOut[4] = {0.f, 0.f, 0.f, 0.f};

    for (int it = 0; it < 5; it++) {
      const float* uin = (it == 0) ? up0 : ((it & 1) ? upB : upA);
      float* uout = (it & 1) ? upA : upB;
      float part = 0.f;
      float um, u0, u1, uImaxV;

      // ---- F0 ----
      {
        if (it == 0) { invRho = 1.f / readSum32(redR, lane); dt = dt0; imax = imax0; }
        else { float m = readMax32(redMax, redIdx, lane, &imax); dt = CFLF / (m + EPSF); }
        um = uin[smm]; u0 = uin[s0]; u1 = uin[s1i];
        uImaxV = uin[imax];
        gup[s0] = 0.f; gup[s1i] = 0.f;
        float rm = rz[smm] * invRho, r0 = rz[s0] * invRho,
              r1 = rz[s1i] * invRho, rp = rz[sp2] * invRho;
        float Fm = um > 0.f ? um * rm : um * r0;
        float F0 = u0 > 0.f ? u0 * r0 : u0 * r1;
        float F1 = u1 > 0.f ? u1 * r1 : u1 * rp;
        float y0 = r0 - dt * (F0 - Fm), y1 = r1 - dt * (F1 - F0);
        z1[s0] = y0; z1[s1i] = y1;
        Ft0a[s0] = F0; Ft0a[s1i] = F1;
        redStoreSum((fabsf(y0) + EPSF) + (fabsf(y1) + EPSF), redSS, lane, wid);
      }
      __syncthreads();

      // ---- F1..F3 ----
#pragma unroll
      for (int h = 1; h < 4; h++) {
        const float* zi = (h == 1) ? z1 : (h == 2 ? z2 : z3);
        float* zo = (h == 1) ? z2 : (h == 2 ? z3 : z4);
        float* Fta = (h == 1) ? Ft1a : (h == 2 ? Ft2a : Ft3a);
        float iS = 1.f / readSum32(redSS + 32 * (h - 1), lane);
        sOut[h - 1] = iS;
        float rm = (fabsf(zi[smm]) + EPSF) * iS, r0 = (fabsf(zi[s0]) + EPSF) * iS,
              r1 = (fabsf(zi[s1i]) + EPSF) * iS, rp = (fabsf(zi[sp2]) + EPSF) * iS;
        float Fm = um > 0.f ? um * rm : um * r0;
        float F0 = u0 > 0.f ? u0 * r0 : u0 * r1;
        float F1 = u1 > 0.f ? u1 * r1 : u1 * rp;
        float y0 = r0 - dt * (F0 - Fm), y1 = r1 - dt * (F1 - F0);
        zo[s0] = y0; zo[s1i] = y1;
        Fta[s0] = F0; Fta[s1i] = F1;
        float o0 = fabsf(y0) + EPSF, o1 = fabsf(y1) + EPSF;
        redStoreSum(o0 + o1, redSS + 32 * h, lane, wid);
        if (h == 3) redStoreSum(sd0 * o0 + sd1 * o1, dotB1, lane, wid);
        __syncthreads();
      }

      // ---- G3..G0 ----
#pragma unroll
      for (int h = 3; h >= 0; h--) {
        const float* zout = (h == 3) ? z4 : (h == 2 ? z3 : (h == 1 ? z2 : z1));
        const float* zin  = (h == 3) ? z3 : (h == 2 ? z2 : (h == 1 ? z1 : rz));
        const float* Fta  = (h == 3) ? Ft3a : (h == 2 ? Ft2a : (h == 1 ? Ft1a : Ft0a));
        const float* grOld = (((h + 1) & 1) ? grB : grA);
        float* grNew = ((h & 1) ? grB : grA);
        const float* dotRd = ((h & 1) ? dotB1 : dotB0);
        float* dotWr = ((h & 1) ? dotB0 : dotB1);

        if (h == 3) sOut[3] = 1.f / readSum32(redSS + 96, lane);
        float iSout = sOut[h];
        float iSin = (h == 0) ? invRho : sOut[h - 1];
        float dotv = readSum32(dotRd, lane) * iSout;

        int idx4[4] = {smm, s0, s1i, sp2};
        float gy4[4];
#pragma unroll
        for (int q = 0; q < 4; q++) {
          int t = idx4[q];
          float yv = zout[t];
          float gin;
          if (h == 3) {
            gin = (q == 1) ? sd0 : ((q == 2) ? sd1 : (1.f - vv[t]) * 0.125f);
          } else {
            gin = grOld[t];
          }
          float gw = (gin - dotv) * iSout;
          gy4[q] = yv > 0.f ? gw : (yv < 0.f ? -gw : 0.f);
        }
        float gym = gy4[0], gy0 = gy4[1], gy1 = gy4[2], gyp = gy4[3];

        float zi0 = zin[s0], zi1 = zin[s1i], zip = zin[sp2];
        float o0, o1, r0, r1, rp;
        if (h == 0) {
          o0 = zi0; o1 = zi1;
          r0 = zi0 * iSin; r1 = zi1 * iSin; rp = zip * iSin;
        } else {
          o0 = fabsf(zi0) + EPSF; o1 = fabsf(zi1) + EPSF;
          r0 = o0 * iSin; r1 = o1 * iSin; rp = (fabsf(zip) + EPSF) * iSin;
        }
        float Ftm = Fta[smm], Ftv0 = Fta[s0], Ftv1 = Fta[s1i];
        part += gy0 * (Ftm - Ftv0) + gy1 * (Ftv0 - Ftv1);
        float gFs0 = dt * (gy1 - gy0), gFm0 = dt * (gy0 - gym), gFs1 = dt * (gyp - gy1);
        gup[s0]  += gFs0 * (u0 > 0.f ? r0 : r1);
        gup[s1i] += gFs1 * (u1 > 0.f ? r1 : rp);
        if (h > 0) {
          float ngr0 = gy0 + (u0 > 0.f ? u0 * gFs0 : 0.f) + (um > 0.f ? 0.f : um * gFm0);
          float ngr1 = gy1 + (u1 > 0.f ? u1 * gFs1 : 0.f) + (u0 > 0.f ? 0.f : u0 * gFs0);
          grNew[s0] = ngr0; grNew[s1i] = ngr1;
          redStoreSum(ngr0 * o0 + ngr1 * o1, dotWr, lane, wid);
        } else {
          redStoreSum(part, redPart, lane, wid);
        }
        __syncthreads();
      }

      // ---- PE': up_{n+1} = up_n - 0.1*M*(gup + argmax corr); max ----
      {
        float gdt = readSum32(redPart, lane);
        float gm = gdt * (-dt * dt * (1.0f / CFLF));
        float sg = uImaxV > 0.f ? 1.f : (uImaxV < 0.f ? -1.f : 0.f);
        float2 c = convM(gup, s0);
        int dd0 = ((imax - s0 + 1024) & SMASK) - 1024;
        int dd1 = ((imax - s1i + 1024) & SMASK) - 1024;
        float corr0 = (dd0 >= -MW && dd0 <= MW) ? gm * sg * MT.M[MW + dd0] : 0.f;
        float corr1 = (dd1 >= -MW && dd1 <= MW) ? gm * sg * MT.M[MW + dd1] : 0.f;
        float n0 = u0 - 0.1f * (c.x + corr0);
        float n1 = u1 - 0.1f * (c.y + corr1);
        uout[s0] = n0; uout[s1i] = n1;
        float a0 = fabsf(n0), a1 = fabsf(n1);
        float mv; int mi;
        if (a0 >= a1) { mv = a0; mi = s0; } else { mv = a1; mi = s1i; }
        redStoreMaxIdx(mv, mi, redMax, redIdx, lane, wid);
      }
      __syncthreads();
    }

    // ---- PF2: outer advect ----
    {
      int mi; float m = readMax32(redMax, redIdx, lane, &mi);
      float dtf = CFLF / (m + EPSF);
      float kap = (ko == 0) ? 0.01f : ((ko == 1) ? 0.005f : 0.0f);
      const float* uf = upB;
      float rm = rz[smm] * invRho, r0 = rz[s0] * invRho,
            r1 = rz[s1i] * invRho, rp = rz[sp2] * invRho;
      float um2 = uf[smm], u02 = uf[s0], u12 = uf[s1i];
      float Fm = um2 > 0.f ? um2 * rm : um2 * r0;
      float F0 = u02 > 0.f ? u02 * r0 : u02 * r1;
      float F1 = u12 > 0.f ? u12 * r1 : u12 * rp;
      float y0 = r0 - dtf * (F0 - Fm) + kap * dtf * (r1 + rm - 2.f * r0);
      float y1 = r1 - dtf * (F1 - F0) + kap * dtf * (rp + r0 - 2.f * r1);
      float o0 = fabsf(y0) + EPSF, o1 = fabsf(y1) + EPSF;
      rzo[s0] = o0; rzo[s1i] = o1;
      redStoreSum(o0 + o1, redF, lane, wid);
    }
    __syncthreads();
    { float* t = rz; rz = rzo; rzo = t; }
  }

  // ---- FO ----
  float t0, t1;
  {
    float invR = 1.f / readSum32(redF, lane);
    t0 = rz[s0] * invR + 0.1f * vvs0;
    t1 = rz[s1i] * invR + 0.1f * vvs1;
    redStoreSum(t0 + t1, redR, lane, wid);
  }
  __syncthreads();
  {
    float invSf = 1.f / readSum32(redR, lane);
    g_rhof[b * Sn + s0] = t0 * invSf;
    g_rhof[b * Sn + s1i] = t1 * invSf;
  }
}

// ------------------------------------------------------------------
// Kernel C (unchanged)
// ------------------------------------------------------------------
__global__ void __launch_bounds__(256) kC(const float* __restrict__ bw,
                                          float* __restrict__ out) {
  int blk = blockIdx.x;
  int b = blk >> 8, k = blk & 255;
  const float* rf = g_rhof + b * Sn;
  float A  = rf[k] * C22;
  float E  = rf[256 + k] * C22;
  float C0 = rf[512 + 2 * k] * 0.5f;
  float C1 = rf[512 + 2 * k + 1] * 0.5f;
  float D0 = rf[1024 + 4 * k] * IR2;
  float D1 = rf[1024 + 4 * k + 1] * IR2;
  float D2 = rf[1024 + 4 * k + 2] * IR2;
  float D3 = rf[1024 + 4 * k + 3] * IR2;

  float s1[8], s2[8], s3[8];
#pragma unroll
  for (int j = 0; j < 8; j++) {
    float Ej = (j < 4) ? E : -E;
    float Cj = (j < 4) ? C0 : C1;
    if ((j & 3) >= 2) Cj = -Cj;
    float Dj = (j >> 1) == 0 ? D0 : ((j >> 1) == 1 ? D1 : ((j >> 1) == 2 ? D2 : D3));
    if (j & 1) Dj = -Dj;
    s1[j] = Ej; s2[j] = Cj; s3[j] = Dj;
  }

  const float4* b0 = (const float4*)bw;
  const float4* b1 = (const float4*)(bw + Dn);
  const float4* b2 = (const float4*)(bw + 2 * Dn);
  const float4* b3 = (const float4*)(bw + 3 * Dn);
  float4* ob = (float4*)(out + ((size_t)b * Sn + (size_t)k * 8) * Dn);

  for (int c = threadIdx.x; c < Dn / 4; c += 256) {
    float4 w0 = b0[c], w1 = b1[c], w2 = b2[c], w3 = b3[c];
#pragma unroll
    for (int j = 0; j < 8; j++) {
      float4 o;
      o.x = A * w0.x + s1[j] * w1.x + s2[j] * w2.x + s3[j] * w3.x;
      o.y = A * w0.y + s1[j] * w1.y + s2[j] * w2.y + s3[j] * w3.y;
      o.z = A * w0.z + s1[j] * w1.z + s2[j] * w2.z + s3[j] * w3.z;
      o.w = A * w0.w + s1[j] * w1.w + s2[j] * w2.w + s3[j] * w3.w;
      __stcs(ob + j * (Dn / 4) + c, o);
    }
  }
}

// ------------------------------------------------------------------
#define SMEMB ((18 * Sn + 512) * 4)

extern "C" void kernel_launch(void* const* d_in, const int* in_sizes, int n_in,
                              void* d_out, int out_size) {
  const float* x   = (const float*)d_in[0];
  const float* w   = (const float*)d_in[1];
  const float* phi = (const float*)d_in[2];
  const float* bw  = (const float*)d_in[3];
  float* out = (float*)d_out;

  cudaFuncSetAttribute((const void*)kB, cudaFuncAttributeMaxDynamicSharedMemorySize, SMEMB);

  kA<<<Bn * 256, 256>>>(x, w);
  kB<<<Bn, 1024, SMEMB>>>(phi);
  kC<<<Bn * 256, 256>>>(bw, out);
}

// round 9
// speedup vs baseline: 2.9907x; 1.1680x over previous
#include <cuda_runtime.h>
#include <math.h>

#define Bn 8
#define Sn 2048
#define Dn 2048
#define SMASK 2047
#define IR2 0.70710678118654752f
#define C22 0.35355339059327379f
#define EPSF 1e-8f
#define CFLF 0.4f
#define SQRTD 45.254833995939045f
#define MW 32

__device__ float g_rho_raw[Bn * Sn];
__device__ float g_pt[Bn * Sn];
__device__ float g_rhof[Bn * Sn];

// ------------------------------------------------------------------
// Compile-time Leray taps L (101) and L^2 taps M (2*MW+1).
// ------------------------------------------------------------------
struct TapsF { float L[101]; };
struct MTapsF { float M[2 * MW + 1]; };

__host__ __device__ constexpr TapsF makeTapsF() {
  double h[103] = {};
  for (int m = -49; m <= 49; m++) {
    int am = m < 0 ? -m : m;
    double term = 1.0;
    for (int i = 0; i < am; i++) term *= 0.5;
    double acc = 0.0;
    for (int k = am; k <= 49; k += 2) {
      acc += term;
      int j = (k + m) / 2;
      term = term * (double)((k + 1) * (k + 2)) / (4.0 * (double)((j + 1) * (k + 1 - j)));
    }
    h[51 + m] = -0.5 * acc;
  }
  TapsF t{};
  for (int m = -50; m <= 50; m++) {
    double v = 2.0 * h[51 + m] - h[51 + m - 1] - h[51 + m + 1];
    t.L[50 + m] = (float)((m == 0 ? 1.0 : 0.0) + v);
  }
  return t;
}

__host__ __device__ constexpr MTapsF makeM() {
  double h[103] = {};
  for (int m = -49; m <= 49; m++) {
    int am = m < 0 ? -m : m;
    double term = 1.0;
    for (int i = 0; i < am; i++) term *= 0.5;
    double acc = 0.0;
    for (int k = am; k <= 49; k += 2) {
      acc += term;
      int j = (k + m) / 2;
      term = term * (double)((k + 1) * (k + 2)) / (4.0 * (double)((j + 1) * (k + 1 - j)));
    }
    h[51 + m] = -0.5 * acc;
  }
  double L[101] = {};
  for (int m = -50; m <= 50; m++) {
    double v = 2.0 * h[51 + m] - h[51 + m - 1] - h[51 + m + 1];
    L[50 + m] = (m == 0 ? 1.0 : 0.0) + v;
  }
  MTapsF t{};
  for (int m = -MW; m <= MW; m++) {
    double acc = 0.0;
    for (int j = -50; j <= 50; j++) {
      int k = m - j;
      if (k >= -50 && k <= 50) acc += L[50 + j] * L[50 + k];
    }
    t.M[MW + m] = (float)acc;
  }
  return t;
}

__constant__ TapsF TAPS = makeTapsF();
__constant__ MTapsF MT = makeM();

// Conv L (101 taps) for 4 outputs at q..q+3 (q % 4 == 0).
__device__ __forceinline__ void convL4(const float* __restrict__ in, int q, float* o) {
  o[0] = o[1] = o[2] = o[3] = 0.f;
  const int base = q + (Sn - 50);
#pragma unroll
  for (int j = 0; j <= 51; j++) {
    int p = (base + 2 * j) & SMASK;
    float2 w = *(const float2*)(in + p);
    const int rel = 2 * j - 50;
#pragma unroll
    for (int e = 0; e < 4; e++) {
      const int m0 = rel - e;
      const int m1 = rel + 1 - e;
      if (m0 >= -50 && m0 <= 50) o[e] = fmaf(TAPS.L[50 + m0], w.x, o[e]);
      if (m1 >= -50 && m1 <= 50) o[e] = fmaf(TAPS.L[50 + m1], w.y, o[e]);
    }
  }
}

// Conv M = L^2 (2*MW+1 taps) for 4 outputs at q..q+3.
__device__ __forceinline__ void convM4(const float* __restrict__ in, int q, float* o) {
  o[0] = o[1] = o[2] = o[3] = 0.f;
  const int base = q + (Sn - MW);
#pragma unroll
  for (int j = 0; j <= MW + 1; j++) {
    int p = (base + 2 * j) & SMASK;
    float2 w = *(const float2*)(in + p);
    const int rel = 2 * j - MW;
#pragma unroll
    for (int e = 0; e < 4; e++) {
      const int m0 = rel - e;
      const int m1 = rel + 1 - e;
      if (m0 >= -MW && m0 <= MW) o[e] = fmaf(MT.M[MW + m0], w.x, o[e]);
      if (m1 >= -MW && m1 <= MW) o[e] = fmaf(MT.M[MW + m1], w.y, o[e]);
    }
  }
}

// ------------------------------------------------------------------
// Kernel A (unchanged)
// ------------------------------------------------------------------
__global__ void __launch_bounds__(256) kA(const float* __restrict__ x,
                                          const float* __restrict__ w) {
  int blk = blockIdx.x;
  int b = blk >> 8, k = blk & 255;
  const float4* base = (const float4*)(x + ((size_t)b * Sn + (size_t)k * 8) * Dn);
  const float4* w4 = (const float4*)w;

  float acc[16];
#pragma unroll
  for (int q = 0; q < 16; q++) acc[q] = 0.f;

  for (int c = threadIdx.x; c < Dn / 4; c += 256) {
    float4 xr[8];
#pragma unroll
    for (int j = 0; j < 8; j++) xr[j] = __ldcs(base + j * (Dn / 4) + c);
    float4 wv = w4[c];
#pragma unroll
    for (int comp = 0; comp < 4; comp++) {
      float v0 = ((const float*)&xr[0])[comp];
      float v1 = ((const float*)&xr[1])[comp];
      float v2 = ((const float*)&xr[2])[comp];
      float v3 = ((const float*)&xr[3])[comp];
      float v4 = ((const float*)&xr[4])[comp];
      float v5 = ((const float*)&xr[5])[comp];
      float v6 = ((const float*)&xr[6])[comp];
      float v7 = ((const float*)&xr[7])[comp];
      float wc = ((const float*)&wv)[comp];
      float e0 = v0 + v1, e1 = v2 + v3, e2 = v4 + v5, e3 = v6 + v7;
      float d10 = v0 - v1, d11 = v2 - v3, d12 = v4 - v5, d13 = v6 - v7;
      float a20 = e0 + e1, a21 = e2 + e3;
      float d20 = e0 - e1, d21 = e2 - e3;
      float a3 = a20 + a21, d3 = a20 - a21;
      acc[0] += a3 * a3;   acc[1] += d3 * d3;
      acc[2] += d20 * d20; acc[3] += d21 * d21;
      acc[4] += d10 * d10; acc[5] += d11 * d11;
      acc[6] += d12 * d12; acc[7] += d13 * d13;
      acc[8]  += v0 * wc; acc[9]  += v1 * wc; acc[10] += v2 * wc; acc[11] += v3 * wc;
      acc[12] += v4 * wc; acc[13] += v5 * wc; acc[14] += v6 * wc; acc[15] += v7 * wc;
    }
  }

  __shared__ float red[128];
  int lane = threadIdx.x & 31, wid = threadIdx.x >> 5;
#pragma unroll
  for (int q = 0; q < 16; q++) {
    float val = acc[q];
#pragma unroll
    for (int o = 16; o; o >>= 1) val += __shfl_xor_sync(0xffffffffu, val, o);
    if (lane == 0) red[q * 8 + wid] = val;
  }
  __syncthreads();
  if (threadIdx.x < 16) {
    float s2 = 0.f;
#pragma unroll
    for (int ww = 0; ww < 8; ww++) s2 += red[threadIdx.x * 8 + ww];
    int bs = b * Sn;
    int t = threadIdx.x;
    if (t == 0)      g_rho_raw[bs + k]                      = sqrtf(s2) * C22;
    else if (t == 1) g_rho_raw[bs + 256 + k]                = sqrtf(s2) * C22;
    else if (t < 4)  g_rho_raw[bs + 512 + 2 * k + (t - 2)]  = sqrtf(s2) * 0.5f;
    else if (t < 8)  g_rho_raw[bs + 1024 + 4 * k + (t - 4)] = sqrtf(s2) * IR2;
    else             g_pt[bs + 8 * k + (t - 8)] = s2;
  }
}

// ------------------------------------------------------------------
// Reductions for 16 warps: store 16 partials, read with 1 LDS + 4 shfl.
// ------------------------------------------------------------------
__device__ __forceinline__ void redStoreSum(float v, float* buf, int lane, int wid) {
#pragma unroll
  for (int o = 16; o; o >>= 1) v += __shfl_xor_sync(0xffffffffu, v, o);
  if (lane == 0) buf[wid] = v;
}
__device__ __forceinline__ float readSum16(const float* buf, int lane) {
  float v = buf[lane & 15];
#pragma unroll
  for (int o = 8; o; o >>= 1) v += __shfl_xor_sync(0xffffffffu, v, o);
  return v;
}
__device__ __forceinline__ void redStoreMaxIdx(float v, int idx, float* bv, int* bi,
                                               int lane, int wid) {
#pragma unroll
  for (int o = 16; o; o >>= 1) {
    float ov = __shfl_xor_sync(0xffffffffu, v, o);
    int oi = __shfl_xor_sync(0xffffffffu, idx, o);
    if (ov > v || (ov == v && oi < idx)) { v = ov; idx = oi; }
  }
  if (lane == 0) { bv[wid] = v; bi[wid] = idx; }
}
__device__ __forceinline__ float readMax16(const float* bv, const int* bi, int lane,
                                           int* oi) {
  float v = bv[lane & 15]; int idx = bi[lane & 15];
#pragma unroll
  for (int o = 8; o; o >>= 1) {
    float ov = __shfl_xor_sync(0xffffffffu, v, o);
    int oi2 = __shfl_xor_sync(0xffffffffu, idx, o);
    if (ov > v || (ov == v && oi2 < idx)) { v = ov; idx = oi2; }
  }
  *oi = idx;
  return v;
}

// ------------------------------------------------------------------
// Kernel B: 512 threads, thread t owns elements 4t..4t+3.
// ------------------------------------------------------------------
__global__ void __launch_bounds__(512, 1) kB(const float* __restrict__ phi_g) {
  int b = blockIdx.x;
  extern __shared__ float sm[];
  float* phi_s = sm + 0 * Sn;
  float* vv   = sm + 1 * Sn;
  float* rb0  = sm + 2 * Sn;
  float* rb1  = sm + 3 * Sn;
  float* up0  = sm + 4 * Sn;
  float* upA  = sm + 5 * Sn;
  float* upB  = sm + 6 * Sn;
  float* z1   = sm + 7 * Sn;
  float* z2   = sm + 8 * Sn;
  float* z3   = sm + 9 * Sn;
  float* z4   = sm + 10 * Sn;
  float* Ft0a = sm + 11 * Sn;
  float* Ft1a = sm + 12 * Sn;
  float* Ft2a = sm + 13 * Sn;
  float* Ft3a = sm + 14 * Sn;
  float* grA  = sm + 15 * Sn;
  float* grB  = sm + 16 * Sn;
  float* gup  = sm + 17 * Sn;
  float* red  = sm + 18 * Sn;
  float* redMax = red;                 // 16
  int*   redIdx = (int*)(red + 32);    // 16
  float* redSS  = red + 64;            // 4 x 32 (16 used each)
  float* dotB0  = red + 192;
  float* dotB1  = red + 224;
  float* redPart = red + 256;
  float* redR   = red + 288;
  float* redF   = red + 320;

  const int tid = threadIdx.x;
  const int lane = tid & 31, wid = tid >> 5;
  const int q = 4 * tid;
  const int pm1 = (q + SMASK) & SMASK;
  const int pp4 = (q + 4) & SMASK;

  // ---- I1 ----
  {
    float4 ph = *(const float4*)(phi_g + q);
    *(float4*)(phi_s + q) = ph;
    float4 rr = *(const float4*)(g_rho_raw + b * Sn + q);
    rr.x += EPSF; rr.y += EPSF; rr.z += EPSF; rr.w += EPSF;
    *(float4*)(rb0 + q) = rr;
  }
  if (tid < 256) {
    const float* p = g_pt + b * Sn + tid * 8;
    float v0 = p[0], v1 = p[1], v2 = p[2], v3 = p[3];
    float v4 = p[4], v5 = p[5], v6 = p[6], v7 = p[7];
    float e0 = v0 + v1, e1 = v2 + v3, e2 = v4 + v5, e3 = v6 + v7;
    float d10 = v0 - v1, d11 = v2 - v3, d12 = v4 - v5, d13 = v6 - v7;
    float a20 = e0 + e1, a21 = e2 + e3;
    float d20 = e0 - e1, d21 = e2 - e3;
    float a3 = a20 + a21, d3 = a20 - a21;
    vv[tid]               = fabsf(a3) * C22 * SQRTD;
    vv[256 + tid]         = fabsf(d3) * C22 * SQRTD;
    vv[512 + 2 * tid]     = fabsf(d20) * 0.5f * SQRTD;
    vv[512 + 2 * tid + 1] = fabsf(d21) * 0.5f * SQRTD;
    vv[1024 + 4 * tid]     = fabsf(d10) * IR2 * SQRTD;
    vv[1024 + 4 * tid + 1] = fabsf(d11) * IR2 * SQRTD;
    vv[1024 + 4 * tid + 2] = fabsf(d12) * IR2 * SQRTD;
    vv[1024 + 4 * tid + 3] = fabsf(d13) * IR2 * SQRTD;
  }
  __syncthreads();
  // ---- I2 ----
  float4 rawq = *(const float4*)(vv + q);
  float rawp = vv[pp4];
  {
    float4 rq = *(const float4*)(rb0 + q);
    redStoreSum((rq.x + rq.y) + (rq.z + rq.w), redF, lane, wid);
    redStoreSum((rawq.x + rawq.y) + (rawq.z + rawq.w) + 4.f * EPSF, redR, lane, wid);
  }
  __syncthreads();
  // ---- I3: normalize v, gup = grad1(v) ----
  float vq0, vq1, vq2, vq3, sd0, sd1, sd2, sd3;
  {
    float inv = 1.f / readSum16(redR, lane);
    vq0 = (rawq.x + EPSF) * inv; vq1 = (rawq.y + EPSF) * inv;
    vq2 = (rawq.z + EPSF) * inv; vq3 = (rawq.w + EPSF) * inv;
    float4 vs = make_float4(vq0, vq1, vq2, vq3);
    *(float4*)(vv + q) = vs;
    sd0 = (1.f - vq0) * 0.125f; sd1 = (1.f - vq1) * 0.125f;
    sd2 = (1.f - vq2) * 0.125f; sd3 = (1.f - vq3) * 0.125f;
    float4 g = make_float4((rawq.y - rawq.x) * inv, (rawq.z - rawq.y) * inv,
                           (rawq.w - rawq.z) * inv, (rawp - rawq.w) * inv);
    *(float4*)(gup + q) = g;
  }
  __syncthreads();
  // ---- I4b: up0 = L * grad1(v); max ----
  {
    float c[4];
    convL4(gup, q, c);
    *(float4*)(up0 + q) = make_float4(c[0], c[1], c[2], c[3]);
    float mv = -1.f; int mi = 0;
#pragma unroll
    for (int e = 0; e < 4; e++) {
      float a = fabsf(c[e]);
      if (a > mv) { mv = a; mi = q + e; }
    }
    redStoreMaxIdx(mv, mi, redMax, redIdx, lane, wid);
  }
  __syncthreads();

  float dt0 = 0.f; int imax0 = 0;
  float invRho = 0.f;
  float* rz = rb0;
  float* rzo = rb1;

  for (int ko = 0; ko < 3; ko++) {
    // ---- PR1: reaction ----
    {
      if (ko == 0) {
        int mi; float m = readMax16(redMax, redIdx, lane, &mi);
        dt0 = CFLF / (m + EPSF); imax0 = mi;
      }
      float invR = 1.f / readSum16(redF, lane);
      float4 rq = *(const float4*)(rz + q);
      float4 ph = *(const float4*)(phi_s + q);
      float w0 = rq.x * invR, w1 = rq.y * invR, w2 = rq.z * invR, w3 = rq.w * invR;
      w0 = w0 * expf(-0.1f * (ph.x + logf(w0))) + EPSF;
      w1 = w1 * expf(-0.1f * (ph.y + logf(w1))) + EPSF;
      w2 = w2 * expf(-0.1f * (ph.z + logf(w2))) + EPSF;
      w3 = w3 * expf(-0.1f * (ph.w + logf(w3))) + EPSF;
      *(float4*)(rz + q) = make_float4(w0, w1, w2, w3);
      redStoreSum((w0 + w1) + (w2 + w3), redR, lane, wid);
    }
    __syncthreads();

    float dt = 0.f; int imax = 0;
    float sOut[4] = {0.f, 0.f, 0.f, 0.f};

    for (int it = 0; it < 5; it++) {
      const float* uin = (it == 0) ? up0 : ((it & 1) ? upB : upA);
      float* uout = (it & 1) ? upA : upB;
      float part = 0.f;
      float um, u0, u1, u2, u3, uImaxV;

      // ---- F0 ----
      {
        if (it == 0) { invRho = 1.f / readSum16(redR, lane); dt = dt0; imax = imax0; }
        else { float m = readMax16(redMax, redIdx, lane, &imax); dt = CFLF / (m + EPSF); }
        um = uin[pm1];
        float4 uq = *(const float4*)(uin + q);
        u0 = uq.x; u1 = uq.y; u2 = uq.z; u3 = uq.w;
        uImaxV = uin[imax];
        *(float4*)(gup + q) = make_float4(0.f, 0.f, 0.f, 0.f);
        float rm = rz[pm1] * invRho, rp = rz[pp4] * invRho;
        float4 rq = *(const float4*)(rz + q);
        float r0 = rq.x * invRho, r1 = rq.y * invRho, r2 = rq.z * invRho, r3 = rq.w * invRho;
        float Fm = um > 0.f ? um * rm : um * r0;
        float F0 = u0 > 0.f ? u0 * r0 : u0 * r1;
        float F1 = u1 > 0.f ? u1 * r1 : u1 * r2;
        float F2 = u2 > 0.f ? u2 * r2 : u2 * r3;
        float F3 = u3 > 0.f ? u3 * r3 : u3 * rp;
        float y0 = r0 - dt * (F0 - Fm), y1 = r1 - dt * (F1 - F0);
        float y2 = r2 - dt * (F2 - F1), y3 = r3 - dt * (F3 - F2);
        *(float4*)(z1 + q) = make_float4(y0, y1, y2, y3);
        *(float4*)(Ft0a + q) = make_float4(F0, F1, F2, F3);
        redStoreSum(((fabsf(y0) + EPSF) + (fabsf(y1) + EPSF)) +
                    ((fabsf(y2) + EPSF) + (fabsf(y3) + EPSF)), redSS, lane, wid);
      }
      __syncthreads();

      // ---- F1..F3 ----
#pragma unroll
      for (int h = 1; h < 4; h++) {
        const float* zi = (h == 1) ? z1 : (h == 2 ? z2 : z3);
        float* zo = (h == 1) ? z2 : (h == 2 ? z3 : z4);
        float* Fta = (h == 1) ? Ft1a : (h == 2 ? Ft2a : Ft3a);
        float iS = 1.f / readSum16(redSS + 32 * (h - 1), lane);
        sOut[h - 1] = iS;
        float rm = (fabsf(zi[pm1]) + EPSF) * iS, rp = (fabsf(zi[pp4]) + EPSF) * iS;
        float4 zq = *(const float4*)(zi + q);
        float r0 = (fabsf(zq.x) + EPSF) * iS, r1 = (fabsf(zq.y) + EPSF) * iS;
        float r2 = (fabsf(zq.z) + EPSF) * iS, r3 = (fabsf(zq.w) + EPSF) * iS;
        float Fm = um > 0.f ? um * rm : um * r0;
        float F0 = u0 > 0.f ? u0 * r0 : u0 * r1;
        float F1 = u1 > 0.f ? u1 * r1 : u1 * r2;
        float F2 = u2 > 0.f ? u2 * r2 : u2 * r3;
        float F3 = u3 > 0.f ? u3 * r3 : u3 * rp;
        float y0 = r0 - dt * (F0 - Fm), y1 = r1 - dt * (F1 - F0);
        float y2 = r2 - dt * (F2 - F1), y3 = r3 - dt * (F3 - F2);
        *(float4*)(zo + q) = make_float4(y0, y1, y2, y3);
        *(float4*)(Fta + q) = make_float4(F0, F1, F2, F3);
        float o0 = fabsf(y0) + EPSF, o1 = fabsf(y1) + EPSF;
        float o2 = fabsf(y2) + EPSF, o3 = fabsf(y3) + EPSF;
        redStoreSum((o0 + o1) + (o2 + o3), redSS + 32 * h, lane, wid);
        if (h == 3)
          redStoreSum((sd0 * o0 + sd1 * o1) + (sd2 * o2 + sd3 * o3), dotB1, lane, wid);
        __syncthreads();
      }

      // ---- G3..G0 ----
#pragma unroll
      for (int h = 3; h >= 0; h--) {
        const float* zout = (h == 3) ? z4 : (h == 2 ? z3 : (h == 1 ? z2 : z1));
        const float* zin  = (h == 3) ? z3 : (h == 2 ? z2 : (h == 1 ? z1 : rz));
        const float* Fta  = (h == 3) ? Ft3a : (h == 2 ? Ft2a : (h == 1 ? Ft1a : Ft0a));
        const float* grOld = (((h + 1) & 1) ? grB : grA);
        float* grNew = ((h & 1) ? grB : grA);
        const float* dotRd = ((h & 1) ? dotB1 : dotB0);
        float* dotWr = ((h & 1) ? dotB0 : dotB1);

        if (h == 3) sOut[3] = 1.f / readSum16(redSS + 96, lane);
        float iSout = sOut[h];
        float iSin = (h == 0) ? invRho : sOut[h - 1];
        float dotv = readSum16(dotRd, lane) * iSout;

        // gy at pm1, q..q+3, pp4
        float gy[6];
        {
          float yv[6], gin[6];
          yv[0] = zout[pm1]; yv[5] = zout[pp4];
          float4 zq = *(const float4*)(zout + q);
          yv[1] = zq.x; yv[2] = zq.y; yv[3] = zq.z; yv[4] = zq.w;
          if (h == 3) {
            gin[0] = (1.f - vv[pm1]) * 0.125f;
            gin[5] = (1.f - vv[pp4]) * 0.125f;
            gin[1] = sd0; gin[2] = sd1; gin[3] = sd2; gin[4] = sd3;
          } else {
            gin[0] = grOld[pm1]; gin[5] = grOld[pp4];
            float4 gq = *(const float4*)(grOld + q);
            gin[1] = gq.x; gin[2] = gq.y; gin[3] = gq.z; gin[4] = gq.w;
          }
#pragma unroll
          for (int e = 0; e < 6; e++) {
            float gw = (gin[e] - dotv) * iSout;
            gy[e] = yv[e] > 0.f ? gw : (yv[e] < 0.f ? -gw : 0.f);
          }
        }

        float zim = zin[pm1], zip = zin[pp4];
        float4 ziq = *(const float4*)(zin + q);
        float o0, o1, o2, o3, r0, r1, r2, r3, rp;
        if (h == 0) {
          o0 = ziq.x; o1 = ziq.y; o2 = ziq.z; o3 = ziq.w;
          r0 = o0 * iSin; r1 = o1 * iSin; r2 = o2 * iSin; r3 = o3 * iSin;
          rp = zip * iSin;
        } else {
          o0 = fabsf(ziq.x) + EPSF; o1 = fabsf(ziq.y) + EPSF;
          o2 = fabsf(ziq.z) + EPSF; o3 = fabsf(ziq.w) + EPSF;
          r0 = o0 * iSin; r1 = o1 * iSin; r2 = o2 * iSin; r3 = o3 * iSin;
          rp = (fabsf(zip) + EPSF) * iSin;
        }
        (void)zim;
        float Ftm = Fta[pm1];
        float4 Fq = *(const float4*)(Fta + q);
        part += gy[1] * (Ftm - Fq.x) + gy[2] * (Fq.x - Fq.y) +
                gy[3] * (Fq.y - Fq.z) + gy[4] * (Fq.z - Fq.w);
        float gFs0 = dt * (gy[2] - gy[1]);
        float gFs1 = dt * (gy[3] - gy[2]);
        float gFs2 = dt * (gy[4] - gy[3]);
        float gFs3 = dt * (gy[5] - gy[4]);
        float gFm0 = dt * (gy[1] - gy[0]);
        {
          float4 gq = *(const float4*)(gup + q);
          gq.x += gFs0 * (u0 > 0.f ? r0 : r1);
          gq.y += gFs1 * (u1 > 0.f ? r1 : r2);
          gq.z += gFs2 * (u2 > 0.f ? r2 : r3);
          gq.w += gFs3 * (u3 > 0.f ? r3 : rp);
          *(float4*)(gup + q) = gq;
        }
        if (h > 0) {
          float ngr0 = gy[1] + (u0 > 0.f ? u0 * gFs0 : 0.f) + (um > 0.f ? 0.f : um * gFm0);
          float ngr1 = gy[2] + (u1 > 0.f ? u1 * gFs1 : 0.f) + (u0 > 0.f ? 0.f : u0 * gFs0);
          float ngr2 = gy[3] + (u2 > 0.f ? u2 * gFs2 : 0.f) + (u1 > 0.f ? 0.f : u1 * gFs1);
          float ngr3 = gy[4] + (u3 > 0.f ? u3 * gFs3 : 0.f) + (u2 > 0.f ? 0.f : u2 * gFs2);
          *(float4*)(grNew + q) = make_float4(ngr0, ngr1, ngr2, ngr3);
          redStoreSum((ngr0 * o0 + ngr1 * o1) + (ngr2 * o2 + ngr3 * o3), dotWr, lane, wid);
        } else {
          redStoreSum(part, redPart, lane, wid);
        }
        __syncthreads();
      }

      // ---- PE': up_{n+1} = up_n - 0.1*M*(gup + argmax corr); max ----
      {
        float gdt = readSum16(redPart, lane);
        float gm = gdt * (-dt * dt * (1.0f / CFLF));
        float sg = uImaxV > 0.f ? 1.f : (uImaxV < 0.f ? -1.f : 0.f);
        float c[4];
        convM4(gup, q, c);
        float uq[4] = {u0, u1, u2, u3};
        float mv = -1.f; int mi = 0;
#pragma unroll
        for (int e = 0; e < 4; e++) {
          int dd = ((imax - (q + e) + 1024) & SMASK) - 1024;
          float corr = (dd >= -MW && dd <= MW) ? gm * sg * MT.M[MW + dd] : 0.f;
          float n = uq[e] - 0.1f * (c[e] + corr);
          c[e] = n;
          float a = fabsf(n);
          if (a > mv) { mv = a; mi = q + e; }
        }
        *(float4*)(uout + q) = make_float4(c[0], c[1], c[2], c[3]);
        redStoreMaxIdx(mv, mi, redMax, redIdx, lane, wid);
      }
      __syncthreads();
    }

    // ---- PF2: outer advect ----
    {
      int mi; float m = readMax16(redMax, redIdx, lane, &mi);
      float dtf = CFLF / (m + EPSF);
      float kap = (ko == 0) ? 0.01f : ((ko == 1) ? 0.005f : 0.0f);
      const float* uf = upB;
      float rm = rz[pm1] * invRho, rp = rz[pp4] * invRho;
      float4 rq = *(const float4*)(rz + q);
      float r0 = rq.x * invRho, r1 = rq.y * invRho, r2 = rq.z * invRho, r3 = rq.w * invRho;
      float um2 = uf[pm1];
      float4 uq = *(const float4*)(uf + q);
      float Fm = um2 > 0.f ? um2 * rm : um2 * r0;
      float F0 = uq.x > 0.f ? uq.x * r0 : uq.x * r1;
      float F1 = uq.y > 0.f ? uq.y * r1 : uq.y * r2;
      float F2 = uq.z > 0.f ? uq.z * r2 : uq.z * r3;
      float F3 = uq.w > 0.f ? uq.w * r3 : uq.w * rp;
      float y0 = r0 - dtf * (F0 - Fm) + kap * dtf * (r1 + rm - 2.f * r0);
      float y1 = r1 - dtf * (F1 - F0) + kap * dtf * (r2 + r0 - 2.f * r1);
      float y2 = r2 - dtf * (F2 - F1) + kap * dtf * (r3 + r1 - 2.f * r2);
      float y3 = r3 - dtf * (F3 - F2) + kap * dtf * (rp + r2 - 2.f * r3);
      float o0 = fabsf(y0) + EPSF, o1 = fabsf(y1) + EPSF;
      float o2 = fabsf(y2) + EPSF, o3 = fabsf(y3) + EPSF;
      *(float4*)(rzo + q) = make_float4(o0, o1, o2, o3);
      redStoreSum((o0 + o1) + (o2 + o3), redF, lane, wid);
    }
    __syncthreads();
    { float* t = rz; rz = rzo; rzo = t; }
  }

  // ---- FO ----
  float t0, t1, t2, t3;
  {
    float invR = 1.f / readSum16(redF, lane);
    float4 rq = *(const float4*)(rz + q);
    t0 = rq.x * invR + 0.1f * vq0;
    t1 = rq.y * invR + 0.1f * vq1;
    t2 = rq.z * invR + 0.1f * vq2;
    t3 = rq.w * invR + 0.1f * vq3;
    redStoreSum((t0 + t1) + (t2 + t3), redR, lane, wid);
  }
  __syncthreads();
  {
    float invSf = 1.f / readSum16(redR, lane);
    float4 o = make_float4(t0 * invSf, t1 * invSf, t2 * invSf, t3 * invSf);
    *(float4*)(g_rhof + b * Sn + q) = o;
  }
}

// ------------------------------------------------------------------
// Kernel C (unchanged)
// ------------------------------------------------------------------
__global__ void __launch_bounds__(256) kC(const float* __restrict__ bw,
                                          float* __restrict__ out) {
  int blk = blockIdx.x;
  int b = blk >> 8, k = blk & 255;
  const float* rf = g_rhof + b * Sn;
  float A  = rf[k] * C22;
  float E  = rf[256 + k] * C22;
  float C0 = rf[512 + 2 * k] * 0.5f;
  float C1 = rf[512 + 2 * k + 1] * 0.5f;
  float D0 = rf[1024 + 4 * k] * IR2;
  float D1 = rf[1024 + 4 * k + 1] * IR2;
  float D2 = rf[1024 + 4 * k + 2] * IR2;
  float D3 = rf[1024 + 4 * k + 3] * IR2;

  float s1[8], s2[8], s3[8];
#pragma unroll
  for (int j = 0; j < 8; j++) {
    float Ej = (j < 4) ? E : -E;
    float Cj = (j < 4) ? C0 : C1;
    if ((j & 3) >= 2) Cj = -Cj;
    float Dj = (j >> 1) == 0 ? D0 : ((j >> 1) == 1 ? D1 : ((j >> 1) == 2 ? D2 : D3));
    if (j & 1) Dj = -Dj;
    s1[j] = Ej; s2[j] = Cj; s3[j] = Dj;
  }

  const float4* b0 = (const float4*)bw;
  const float4* b1 = (const float4*)(bw + Dn);
  const float4* b2 = (const float4*)(bw + 2 * Dn);
  const float4* b3 = (const float4*)(bw + 3 * Dn);
  float4* ob = (float4*)(out + ((size_t)b * Sn + (size_t)k * 8) * Dn);

  for (int c = threadIdx.x; c < Dn / 4; c += 256) {
    float4 w0 = b0[c], w1 = b1[c], w2 = b2[c], w3 = b3[c];
#pragma unroll
    for (int j = 0; j < 8; j++) {
      float4 o;
      o.x = A * w0.x + s1[j] * w1.x + s2[j] * w2.x + s3[j] * w3.x;
      o.y = A * w0.y + s1[j] * w1.y + s2[j] * w2.y + s3[j] * w3.y;
      o.z = A * w0.z + s1[j] * w1.z + s2[j] * w2.z + s3[j] * w3.z;
      o.w = A * w0.w + s1[j] * w1.w + s2[j] * w2.w + s3[j] * w3.w;
      __stcs(ob + j * (Dn / 4) + c, o);
    }
  }
}

// ------------------------------------------------------------------
#define SMEMB ((18 * Sn + 512) * 4)

extern "C" void kernel_launch(void* const* d_in, const int* in_sizes, int n_in,
                              void* d_out, int out_size) {
  const float* x   = (const float*)d_in[0];
  const float* w   = (const float*)d_in[1];
  const float* phi = (const float*)d_in[2];
  const float* bw  = (const float*)d_in[3];
  float* out = (float*)d_out;

  cudaFuncSetAttribute((const void*)kB, cudaFuncAttributeMaxDynamicSharedMemorySize, SMEMB);

  kA<<<Bn * 256, 256>>>(x, w);
  kB<<<Bn, 512, SMEMB>>>(phi);
  kC<<<Bn * 256, 256>>>(bw, out);
}

// round 10
// speedup vs baseline: 3.0248x; 1.0114x over previous
#include <cuda_runtime.h>
#include <math.h>

#define Bn 8
#define Sn 2048
#define Dn 2048
#define SMASK 2047
#define IR2 0.70710678118654752f
#define C22 0.35355339059327379f
#define EPSF 1e-8f
#define CFLF 0.4f
#define SQRTD 45.254833995939045f
#define MW 32

__device__ float g_rho_raw[Bn * Sn];
__device__ float g_pt[Bn * Sn];
__device__ float g_rhof[Bn * Sn];

// ------------------------------------------------------------------
// Compile-time Leray taps L (101) and L^2 taps M (2*MW+1).
// ------------------------------------------------------------------
struct TapsF { float L[101]; };
struct MTapsF { float M[2 * MW + 1]; };

__host__ __device__ constexpr TapsF makeTapsF() {
  double h[103] = {};
  for (int m = -49; m <= 49; m++) {
    int am = m < 0 ? -m : m;
    double term = 1.0;
    for (int i = 0; i < am; i++) term *= 0.5;
    double acc = 0.0;
    for (int k = am; k <= 49; k += 2) {
      acc += term;
      int j = (k + m) / 2;
      term = term * (double)((k + 1) * (k + 2)) / (4.0 * (double)((j + 1) * (k + 1 - j)));
    }
    h[51 + m] = -0.5 * acc;
  }
  TapsF t{};
  for (int m = -50; m <= 50; m++) {
    double v = 2.0 * h[51 + m] - h[51 + m - 1] - h[51 + m + 1];
    t.L[50 + m] = (float)((m == 0 ? 1.0 : 0.0) + v);
  }
  return t;
}

__host__ __device__ constexpr MTapsF makeM() {
  double h[103] = {};
  for (int m = -49; m <= 49; m++) {
    int am = m < 0 ? -m : m;
    double term = 1.0;
    for (int i = 0; i < am; i++) term *= 0.5;
    double acc = 0.0;
    for (int k = am; k <= 49; k += 2) {
      acc += term;
      int j = (k + m) / 2;
      term = term * (double)((k + 1) * (k + 2)) / (4.0 * (double)((j + 1) * (k + 1 - j)));
    }
    h[51 + m] = -0.5 * acc;
  }
  double L[101] = {};
  for (int m = -50; m <= 50; m++) {
    double v = 2.0 * h[51 + m] - h[51 + m - 1] - h[51 + m + 1];
    L[50 + m] = (m == 0 ? 1.0 : 0.0) + v;
  }
  MTapsF t{};
  for (int m = -MW; m <= MW; m++) {
    double acc = 0.0;
    for (int j = -50; j <= 50; j++) {
      int k = m - j;
      if (k >= -50 && k <= 50) acc += L[50 + j] * L[50 + k];
    }
    t.M[MW + m] = (float)acc;
  }
  return t;
}

__constant__ TapsF TAPS = makeTapsF();
__constant__ MTapsF MT = makeM();

// Conv L (101 taps) for 4 outputs at q..q+3 (q % 4 == 0).
__device__ __forceinline__ void convL4(const float* __restrict__ in, int q, float* o) {
  o[0] = o[1] = o[2] = o[3] = 0.f;
  const int base = q + (Sn - 50);
#pragma unroll
  for (int j = 0; j <= 51; j++) {
    int p = (base + 2 * j) & SMASK;
    float2 w = *(const float2*)(in + p);
    const int rel = 2 * j - 50;
#pragma unroll
    for (int e = 0; e < 4; e++) {
      const int m0 = rel - e;
      const int m1 = rel + 1 - e;
      if (m0 >= -50 && m0 <= 50) o[e] = fmaf(TAPS.L[50 + m0], w.x, o[e]);
      if (m1 >= -50 && m1 <= 50) o[e] = fmaf(TAPS.L[50 + m1], w.y, o[e]);
    }
  }
}

// Conv M = L^2 (2*MW+1 taps) for 4 outputs at q..q+3.
__device__ __forceinline__ void convM4(const float* __restrict__ in, int q, float* o) {
  o[0] = o[1] = o[2] = o[3] = 0.f;
  const int base = q + (Sn - MW);
#pragma unroll
  for (int j = 0; j <= MW + 1; j++) {
    int p = (base + 2 * j) & SMASK;
    float2 w = *(const float2*)(in + p);
    const int rel = 2 * j - MW;
#pragma unroll
    for (int e = 0; e < 4; e++) {
      const int m0 = rel - e;
      const int m1 = rel + 1 - e;
      if (m0 >= -MW && m0 <= MW) o[e] = fmaf(MT.M[MW + m0], w.x, o[e]);
      if (m1 >= -MW && m1 <= MW) o[e] = fmaf(MT.M[MW + m1], w.y, o[e]);
    }
  }
}

// ------------------------------------------------------------------
// Kernel A: higher-occupancy variant (cap regs for 5 blocks/SM).
// ------------------------------------------------------------------
__global__ void __launch_bounds__(256, 5) kA(const float* __restrict__ x,
                                             const float* __restrict__ w) {
  int blk = blockIdx.x;
  int b = blk >> 8, k = blk & 255;
  const float4* base = (const float4*)(x + ((size_t)b * Sn + (size_t)k * 8) * Dn);
  const float4* w4 = (const float4*)w;

  float acc[16];
#pragma unroll
  for (int q = 0; q < 16; q++) acc[q] = 0.f;

  for (int c = threadIdx.x; c < Dn / 4; c += 256) {
    float4 xr[8];
#pragma unroll
    for (int j = 0; j < 8; j++) xr[j] = __ldcs(base + j * (Dn / 4) + c);
    float4 wv = w4[c];
#pragma unroll
    for (int comp = 0; comp < 4; comp++) {
      float v0 = ((const float*)&xr[0])[comp];
      float v1 = ((const float*)&xr[1])[comp];
      float v2 = ((const float*)&xr[2])[comp];
      float v3 = ((const float*)&xr[3])[comp];
      float v4 = ((const float*)&xr[4])[comp];
      float v5 = ((const float*)&xr[5])[comp];
      float v6 = ((const float*)&xr[6])[comp];
      float v7 = ((const float*)&xr[7])[comp];
      float wc = ((const float*)&wv)[comp];
      float e0 = v0 + v1, e1 = v2 + v3, e2 = v4 + v5, e3 = v6 + v7;
      float d10 = v0 - v1, d11 = v2 - v3, d12 = v4 - v5, d13 = v6 - v7;
      float a20 = e0 + e1, a21 = e2 + e3;
      float d20 = e0 - e1, d21 = e2 - e3;
      float a3 = a20 + a21, d3 = a20 - a21;
      acc[0] += a3 * a3;   acc[1] += d3 * d3;
      acc[2] += d20 * d20; acc[3] += d21 * d21;
      acc[4] += d10 * d10; acc[5] += d11 * d11;
      acc[6] += d12 * d12; acc[7] += d13 * d13;
      acc[8]  += v0 * wc; acc[9]  += v1 * wc; acc[10] += v2 * wc; acc[11] += v3 * wc;
      acc[12] += v4 * wc; acc[13] += v5 * wc; acc[14] += v6 * wc; acc[15] += v7 * wc;
    }
  }

  __shared__ float red[128];
  int lane = threadIdx.x & 31, wid = threadIdx.x >> 5;
#pragma unroll
  for (int q = 0; q < 16; q++) {
    float val = acc[q];
#pragma unroll
    for (int o = 16; o; o >>= 1) val += __shfl_xor_sync(0xffffffffu, val, o);
    if (lane == 0) red[q * 8 + wid] = val;
  }
  __syncthreads();
  if (threadIdx.x < 16) {
    float s2 = 0.f;
#pragma unroll
    for (int ww = 0; ww < 8; ww++) s2 += red[threadIdx.x * 8 + ww];
    int bs = b * Sn;
    int t = threadIdx.x;
    if (t == 0)      g_rho_raw[bs + k]                      = sqrtf(s2) * C22;
    else if (t == 1) g_rho_raw[bs + 256 + k]                = sqrtf(s2) * C22;
    else if (t < 4)  g_rho_raw[bs + 512 + 2 * k + (t - 2)]  = sqrtf(s2) * 0.5f;
    else if (t < 8)  g_rho_raw[bs + 1024 + 4 * k + (t - 4)] = sqrtf(s2) * IR2;
    else             g_pt[bs + 8 * k + (t - 8)] = s2;
  }
}

// ------------------------------------------------------------------
// Reductions for 16 warps.
// ------------------------------------------------------------------
__device__ __forceinline__ void redStoreSum(float v, float* buf, int lane, int wid) {
#pragma unroll
  for (int o = 16; o; o >>= 1) v += __shfl_xor_sync(0xffffffffu, v, o);
  if (lane == 0) buf[wid] = v;
}
__device__ __forceinline__ float readSum16(const float* buf, int lane) {
  float v = buf[lane & 15];
#pragma unroll
  for (int o = 8; o; o >>= 1) v += __shfl_xor_sync(0xffffffffu, v, o);
  return v;
}
__device__ __forceinline__ void redStoreMaxIdx(float v, int idx, float* bv, int* bi,
                                               int lane, int wid) {
#pragma unroll
  for (int o = 16; o; o >>= 1) {
    float ov = __shfl_xor_sync(0xffffffffu, v, o);
    int oi = __shfl_xor_sync(0xffffffffu, idx, o);
    if (ov > v || (ov == v && oi < idx)) { v = ov; idx = oi; }
  }
  if (lane == 0) { bv[wid] = v; bi[wid] = idx; }
}
__device__ __forceinline__ float readMax16(const float* bv, const int* bi, int lane,
                                           int* oi) {
  float v = bv[lane & 15]; int idx = bi[lane & 15];
#pragma unroll
  for (int o = 8; o; o >>= 1) {
    float ov = __shfl_xor_sync(0xffffffffu, v, o);
    int oi2 = __shfl_xor_sync(0xffffffffu, idx, o);
    if (ov > v || (ov == v && oi2 < idx)) { v = ov; idx = oi2; }
  }
  *oi = idx;
  return v;
}

// ------------------------------------------------------------------
// Kernel B: 512 threads, quad layout; forward horizon fused into ONE
// phase via unnormalized advection (linear in rho given u) with
// redundant halo-4 compute; scalars resolved after one barrier.
// ------------------------------------------------------------------
__global__ void __launch_bounds__(512, 1) kB(const float* __restrict__ phi_g) {
  int b = blockIdx.x;
  extern __shared__ float sm[];
  float* phi_s = sm + 0 * Sn;
  float* vv   = sm + 1 * Sn;
  float* rb0  = sm + 2 * Sn;
  float* rb1  = sm + 3 * Sn;
  float* up0  = sm + 4 * Sn;
  float* upA  = sm + 5 * Sn;
  float* upB  = sm + 6 * Sn;
  float* z1   = sm + 7 * Sn;
  float* z2   = sm + 8 * Sn;
  float* z3   = sm + 9 * Sn;
  float* z4   = sm + 10 * Sn;
  float* Ft0a = sm + 11 * Sn;
  float* Ft1a = sm + 12 * Sn;
  float* Ft2a = sm + 13 * Sn;
  float* Ft3a = sm + 14 * Sn;
  float* grA  = sm + 15 * Sn;
  float* grB  = sm + 16 * Sn;
  float* gup  = sm + 17 * Sn;
  float* red  = sm + 18 * Sn;
  float* redMax = red;
  int*   redIdx = (int*)(red + 32);
  float* redSS  = red + 64;            // 4 x 32: raw sums of z~_1..4
  float* dotB0  = red + 192;
  float* dotB1  = red + 224;
  float* redPart = red + 256;
  float* redR   = red + 288;
  float* redF   = red + 320;

  const int tid = threadIdx.x;
  const int lane = tid & 31, wid = tid >> 5;
  const int q = 4 * tid;
  const int pm1 = (q + SMASK) & SMASK;
  const int pp4 = (q + 4) & SMASK;

  // ---- I1 ----
  {
    float4 ph = *(const float4*)(phi_g + q);
    *(float4*)(phi_s + q) = ph;
    float4 rr = *(const float4*)(g_rho_raw + b * Sn + q);
    rr.x += EPSF; rr.y += EPSF; rr.z += EPSF; rr.w += EPSF;
    *(float4*)(rb0 + q) = rr;
  }
  if (tid < 256) {
    const float* p = g_pt + b * Sn + tid * 8;
    float v0 = p[0], v1 = p[1], v2 = p[2], v3 = p[3];
    float v4 = p[4], v5 = p[5], v6 = p[6], v7 = p[7];
    float e0 = v0 + v1, e1 = v2 + v3, e2 = v4 + v5, e3 = v6 + v7;
    float d10 = v0 - v1, d11 = v2 - v3, d12 = v4 - v5, d13 = v6 - v7;
    float a20 = e0 + e1, a21 = e2 + e3;
    float d20 = e0 - e1, d21 = e2 - e3;
    float a3 = a20 + a21, d3 = a20 - a21;
    vv[tid]               = fabsf(a3) * C22 * SQRTD;
    vv[256 + tid]         = fabsf(d3) * C22 * SQRTD;
    vv[512 + 2 * tid]     = fabsf(d20) * 0.5f * SQRTD;
    vv[512 + 2 * tid + 1] = fabsf(d21) * 0.5f * SQRTD;
    vv[1024 + 4 * tid]     = fabsf(d10) * IR2 * SQRTD;
    vv[1024 + 4 * tid + 1] = fabsf(d11) * IR2 * SQRTD;
    vv[1024 + 4 * tid + 2] = fabsf(d12) * IR2 * SQRTD;
    vv[1024 + 4 * tid + 3] = fabsf(d13) * IR2 * SQRTD;
  }
  __syncthreads();
  // ---- I2 ----
  float4 rawq = *(const float4*)(vv + q);
  float rawp = vv[pp4];
  {
    float4 rq = *(const float4*)(rb0 + q);
    redStoreSum((rq.x + rq.y) + (rq.z + rq.w), redF, lane, wid);
    redStoreSum((rawq.x + rawq.y) + (rawq.z + rawq.w) + 4.f * EPSF, redR, lane, wid);
  }
  __syncthreads();
  // ---- I3: normalize v, gup = grad1(v) ----
  float vq0, vq1, vq2, vq3, sd0, sd1, sd2, sd3;
  {
    float inv = 1.f / readSum16(redR, lane);
    vq0 = (rawq.x + EPSF) * inv; vq1 = (rawq.y + EPSF) * inv;
    vq2 = (rawq.z + EPSF) * inv; vq3 = (rawq.w + EPSF) * inv;
    *(float4*)(vv + q) = make_float4(vq0, vq1, vq2, vq3);
    sd0 = (1.f - vq0) * 0.125f; sd1 = (1.f - vq1) * 0.125f;
    sd2 = (1.f - vq2) * 0.125f; sd3 = (1.f - vq3) * 0.125f;
    float4 g = make_float4((rawq.y - rawq.x) * inv, (rawq.z - rawq.y) * inv,
                           (rawq.w - rawq.z) * inv, (rawp - rawq.w) * inv);
    *(float4*)(gup + q) = g;
  }
  __syncthreads();
  // ---- I4b: up0 = L * grad1(v); max ----
  {
    float c[4];
    convL4(gup, q, c);
    *(float4*)(up0 + q) = make_float4(c[0], c[1], c[2], c[3]);
    float mv = -1.f; int mi = 0;
#pragma unroll
    for (int e = 0; e < 4; e++) {
      float a = fabsf(c[e]);
      if (a > mv) { mv = a; mi = q + e; }
    }
    redStoreMaxIdx(mv, mi, redMax, redIdx, lane, wid);
  }
  __syncthreads();

  float dt0 = 0.f; int imax0 = 0;
  float invRho = 0.f, Rho = 0.f, E = 0.f;
  float* rz = rb0;
  float* rzo = rb1;

  for (int ko = 0; ko < 3; ko++) {
    // ---- PR1: reaction ----
    {
      if (ko == 0) {
        int mi; float m = readMax16(redMax, redIdx, lane, &mi);
        dt0 = CFLF / (m + EPSF); imax0 = mi;
      }
      float invR = 1.f / readSum16(redF, lane);
      float4 rq = *(const float4*)(rz + q);
      float4 ph = *(const float4*)(phi_s + q);
      float w0 = rq.x * invR, w1 = rq.y * invR, w2 = rq.z * invR, w3 = rq.w * invR;
      w0 = w0 * expf(-0.1f * (ph.x + logf(w0))) + EPSF;
      w1 = w1 * expf(-0.1f * (ph.y + logf(w1))) + EPSF;
      w2 = w2 * expf(-0.1f * (ph.z + logf(w2))) + EPSF;
      w3 = w3 * expf(-0.1f * (ph.w + logf(w3))) + EPSF;
      *(float4*)(rz + q) = make_float4(w0, w1, w2, w3);
      redStoreSum((w0 + w1) + (w2 + w3), redR, lane, wid);
    }
    __syncthreads();

    float dt = 0.f; int imax = 0;

    for (int it = 0; it < 5; it++) {
      const float* uin = (it == 0) ? up0 : ((it & 1) ? upB : upA);
      float* uout = (it & 1) ? upA : upB;
      float part = 0.f;
      float um, u0, u1, u2, u3, uImaxV;

      // ---- FF: fused forward horizon (4 advect stages, 1 phase) ----
      {
        if (it == 0) {
          Rho = readSum16(redR, lane); invRho = 1.f / Rho;
          E = EPSF * Rho;
          dt = dt0; imax = imax0;
        } else {
          float m = readMax16(redMax, redIdx, lane, &imax);
          dt = CFLF / (m + EPSF);
        }
        float U[12], L[12];
        {
          float4 t = *(const float4*)(uin + ((q + Sn - 4) & SMASK));
          U[0] = t.x; U[1] = t.y; U[2] = t.z; U[3] = t.w;
        }
        {
          float4 t = *(const float4*)(uin + q);
          U[4] = t.x; U[5] = t.y; U[6] = t.z; U[7] = t.w;
        }
        {
          float4 t = *(const float4*)(uin + ((q + 4) & SMASK));
          U[8] = t.x; U[9] = t.y; U[10] = t.z; U[11] = t.w;
        }
        {
          float4 t = *(const float4*)(rz + ((q + Sn - 4) & SMASK));
          L[0] = t.x; L[1] = t.y; L[2] = t.z; L[3] = t.w;
        }
        {
          float4 t = *(const float4*)(rz + q);
          L[4] = t.x; L[5] = t.y; L[6] = t.z; L[7] = t.w;
        }
        {
          float4 t = *(const float4*)(rz + ((q + 4) & SMASK));
          L[8] = t.x; L[9] = t.y; L[10] = t.z; L[11] = t.w;
        }
        um = U[3]; u0 = U[4]; u1 = U[5]; u2 = U[6]; u3 = U[7];
        uImaxV = uin[imax];
        *(float4*)(gup + q) = make_float4(0.f, 0.f, 0.f, 0.f);
        float* zArr[4]  = {z1, z2, z3, z4};
        float* FtArr[4] = {Ft0a, Ft1a, Ft2a, Ft3a};
#pragma unroll
        for (int h = 0; h < 4; h++) {
          const int lo = 1 + h, hi = 10 - h;
          float F[11], Y[12];
#pragma unroll
          for (int i = 0; i < 11; i++)
            if (i >= lo - 1 && i <= hi)
              F[i] = U[i] > 0.f ? U[i] * L[i] : U[i] * L[i + 1];
#pragma unroll
          for (int i = 0; i < 12; i++)
            if (i >= lo && i <= hi) Y[i] = L[i] - dt * (F[i] - F[i - 1]);
          *(float4*)(zArr[h] + q)  = make_float4(Y[4], Y[5], Y[6], Y[7]);
          *(float4*)(FtArr[h] + q) = make_float4(F[4], F[5], F[6], F[7]);
#pragma unroll
          for (int i = 0; i < 12; i++)
            if (i >= lo && i <= hi) L[i] = fabsf(Y[i]) + E;
          redStoreSum((L[4] + L[5]) + (L[6] + L[7]), redSS + 32 * h, lane, wid);
          if (h == 3)
            redStoreSum((sd0 * L[4] + sd1 * L[5]) + (sd2 * L[6] + sd3 * L[7]),
                        dotB1, lane, wid);
        }
      }
      __syncthreads();

      // ---- G3..G0: backward (scales resolved from raw sums) ----
      float S1 = 0.f, S2 = 0.f, S3 = 0.f, S4 = 0.f;
      float iS1 = 0.f, iS2 = 0.f, iS3 = 0.f, iS4 = 0.f;
#pragma unroll
      for (int h = 3; h >= 0; h--) {
        const float* zout = (h == 3) ? z4 : (h == 2 ? z3 : (h == 1 ? z2 : z1));
        const float* zin  = (h == 3) ? z3 : (h == 2 ? z2 : (h == 1 ? z1 : rz));
        const float* Fta  = (h == 3) ? Ft3a : (h == 2 ? Ft2a : (h == 1 ? Ft1a : Ft0a));
        const float* grOld = (((h + 1) & 1) ? grB : grA);
        float* grNew = ((h & 1) ? grB : grA);
        const float* dotRd = ((h & 1) ? dotB1 : dotB0);
        float* dotWr = ((h & 1) ? dotB0 : dotB1);

        if (h == 3) {
          S1 = readSum16(redSS + 0, lane);  iS1 = 1.f / S1;
          S2 = readSum16(redSS + 32, lane); iS2 = 1.f / S2;
          S3 = readSum16(redSS + 64, lane); iS3 = 1.f / S3;
          S4 = readSum16(redSS + 96, lane); iS4 = 1.f / S4;
        }
        const float iSoutN = (h == 3) ? iS4 : (h == 2 ? iS3 : (h == 1 ? iS2 : iS1));
        const float Sh     = (h == 3) ? S3 : (h == 2 ? S2 : (h == 1 ? S1 : Rho));
        const float iSh    = (h == 3) ? iS3 : (h == 2 ? iS2 : (h == 1 ? iS1 : invRho));
        const float gwScale = Sh * iSoutN;
        float dotv = readSum16(dotRd, lane) * iSoutN;

        // gy at pm1, q..q+3, pp4 (true-variable gradient wrt y)
        float gy[6];
        {
          float yv[6], gin[6];
          yv[0] = zout[pm1]; yv[5] = zout[pp4];
          float4 zq = *(const float4*)(zout + q);
          yv[1] = zq.x; yv[2] = zq.y; yv[3] = zq.z; yv[4] = zq.w;
          if (h == 3) {
            gin[0] = (1.f - vv[pm1]) * 0.125f;
            gin[5] = (1.f - vv[pp4]) * 0.125f;
            gin[1] = sd0; gin[2] = sd1; gin[3] = sd2; gin[4] = sd3;
          } else {
            gin[0] = grOld[pm1]; gin[5] = grOld[pp4];
            float4 gq = *(const float4*)(grOld + q);
            gin[1] = gq.x; gin[2] = gq.y; gin[3] = gq.z; gin[4] = gq.w;
          }
#pragma unroll
          for (int e = 0; e < 6; e++) {
            float gw = (gin[e] - dotv) * gwScale;
            gy[e] = yv[e] > 0.f ? gw : (yv[e] < 0.f ? -gw : 0.f);
          }
        }

        float zip = zin[pp4];
        float4 ziq = *(const float4*)(zin + q);
        float o0, o1, o2, o3, r0, r1, r2, r3, rp;
        if (h == 0) {
          o0 = ziq.x; o1 = ziq.y; o2 = ziq.z; o3 = ziq.w;
          rp = zip * iSh;
        } else {
          o0 = fabsf(ziq.x) + E; o1 = fabsf(ziq.y) + E;
          o2 = fabsf(ziq.z) + E; o3 = fabsf(ziq.w) + E;
          zip = fabsf(zip) + E;
          rp = zip * iSh;
        }
        r0 = o0 * iSh; r1 = o1 * iSh; r2 = o2 * iSh; r3 = o3 * iSh;

        float Ftm = Fta[pm1];
        float4 Fq = *(const float4*)(Fta + q);
        part += iSh * (gy[1] * (Ftm - Fq.x) + gy[2] * (Fq.x - Fq.y) +
                       gy[3] * (Fq.y - Fq.z) + gy[4] * (Fq.z - Fq.w));
        float gFs0 = dt * (gy[2] - gy[1]);
        float gFs1 = dt * (gy[3] - gy[2]);
        float gFs2 = dt * (gy[4] - gy[3]);
        float gFs3 = dt * (gy[5] - gy[4]);
        float gFm0 = dt * (gy[1] - gy[0]);
        {
          float4 gq = *(const float4*)(gup + q);
          gq.x += gFs0 * (u0 > 0.f ? r0 : r1);
          gq.y += gFs1 * (u1 > 0.f ? r1 : r2);
          gq.z += gFs2 * (u2 > 0.f ? r2 : r3);
          gq.w += gFs3 * (u3 > 0.f ? r3 : rp);
          *(float4*)(gup + q) = gq;
        }
        if (h > 0) {
          float ngr0 = gy[1] + (u0 > 0.f ? u0 * gFs0 : 0.f) + (um > 0.f ? 0.f : um * gFm0);
          float ngr1 = gy[2] + (u1 > 0.f ? u1 * gFs1 : 0.f) + (u0 > 0.f ? 0.f : u0 * gFs0);
          float ngr2 = gy[3] + (u2 > 0.f ? u2 * gFs2 : 0.f) + (u1 > 0.f ? 0.f : u1 * gFs1);
          float ngr3 = gy[4] + (u3 > 0.f ? u3 * gFs3 : 0.f) + (u2 > 0.f ? 0.f : u2 * gFs2);
          *(float4*)(grNew + q) = make_float4(ngr0, ngr1, ngr2, ngr3);
          // raw <gr, z~_h>; consumer scales by iS~_h
          redStoreSum((ngr0 * o0 + ngr1 * o1) + (ngr2 * o2 + ngr3 * o3), dotWr, lane, wid);
        } else {
          redStoreSum(part, redPart, lane, wid);
        }
        __syncthreads();
      }

      // ---- PE': up_{n+1} = up_n - 0.1*M*(gup + argmax corr); max ----
      {
        float gdt = readSum16(redPart, lane);
        float gm = gdt * (-dt * dt * (1.0f / CFLF));
        float sg = uImaxV > 0.f ? 1.f : (uImaxV < 0.f ? -1.f : 0.f);
        float c[4];
        convM4(gup, q, c);
        float uq[4] = {u0, u1, u2, u3};
        float mv = -1.f; int mi = 0;
#pragma unroll
        for (int e = 0; e < 4; e++) {
          int dd = ((imax - (q + e) + 1024) & SMASK) - 1024;
          float corr = (dd >= -MW && dd <= MW) ? gm * sg * MT.M[MW + dd] : 0.f;
          float n = uq[e] - 0.1f * (c[e] + corr);
          c[e] = n;
          float a = fabsf(n);
          if (a > mv) { mv = a; mi = q + e; }
        }
        *(float4*)(uout + q) = make_float4(c[0], c[1], c[2], c[3]);
        redStoreMaxIdx(mv, mi, redMax, redIdx, lane, wid);
      }
      __syncthreads();
    }

    // ---- PF2: outer advect ----
    {
      int mi; float m = readMax16(redMax, redIdx, lane, &mi);
      float dtf = CFLF / (m + EPSF);
      float kap = (ko == 0) ? 0.01f : ((ko == 1) ? 0.005f : 0.0f);
      const float* uf = upB;
      float rm = rz[pm1] * invRho, rp = rz[pp4] * invRho;
      float4 rq = *(const float4*)(rz + q);
      float r0 = rq.x * invRho, r1 = rq.y * invRho, r2 = rq.z * invRho, r3 = rq.w * invRho;
      float um2 = uf[pm1];
      float4 uq = *(const float4*)(uf + q);
      float Fm = um2 > 0.f ? um2 * rm : um2 * r0;
      float F0 = uq.x > 0.f ? uq.x * r0 : uq.x * r1;
      float F1 = uq.y > 0.f ? uq.y * r1 : uq.y * r2;
      float F2 = uq.z > 0.f ? uq.z * r2 : uq.z * r3;
      float F3 = uq.w > 0.f ? uq.w * r3 : uq.w * rp;
      float y0 = r0 - dtf * (F0 - Fm) + kap * dtf * (r1 + rm - 2.f * r0);
      float y1 = r1 - dtf * (F1 - F0) + kap * dtf * (r2 + r0 - 2.f * r1);
      float y2 = r2 - dtf * (F2 - F1) + kap * dtf * (r3 + r1 - 2.f * r2);
      float y3 = r3 - dtf * (F3 - F2) + kap * dtf * (rp + r2 - 2.f * r3);
      float o0 = fabsf(y0) + EPSF, o1 = fabsf(y1) + EPSF;
      float o2 = fabsf(y2) + EPSF, o3 = fabsf(y3) + EPSF;
      *(float4*)(rzo + q) = make_float4(o0, o1, o2, o3);
      redStoreSum((o0 + o1) + (o2 + o3), redF, lane, wid);
    }
    __syncthreads();
    { float* t = rz; rz = rzo; rzo = t; }
  }

  // ---- FO ----
  float t0, t1, t2, t3;
  {
    float invR = 1.f / readSum16(redF, lane);
    float4 rq = *(const float4*)(rz + q);
    t0 = rq.x * invR + 0.1f * vq0;
    t1 = rq.y * invR + 0.1f * vq1;
    t2 = rq.z * invR + 0.1f * vq2;
    t3 = rq.w * invR + 0.1f * vq3;
    redStoreSum((t0 + t1) + (t2 + t3), redR, lane, wid);
  }
  __syncthreads();
  {
    float invSf = 1.f / readSum16(redR, lane);
    *(float4*)(g_rhof + b * Sn + q) =
        make_float4(t0 * invSf, t1 * invSf, t2 * invSf, t3 * invSf);
  }
}

// ------------------------------------------------------------------
// Kernel C: 512 threads, single column pass.
// ------------------------------------------------------------------
__global__ void __launch_bounds__(512) kC(const float* __restrict__ bw,
                                          float* __restrict__ out) {
  int blk = blockIdx.x;
  int b = blk >> 8, k = blk & 255;
  const float* rf = g_rhof + b * Sn;
  float A  = rf[k] * C22;
  float E  = rf[256 + k] * C22;
  float C0 = rf[512 + 2 * k] * 0.5f;
  float C1 = rf[512 + 2 * k + 1] * 0.5f;
  float D0 = rf[1024 + 4 * k] * IR2;
  float D1 = rf[1024 + 4 * k + 1] * IR2;
  float D2 = rf[1024 + 4 * k + 2] * IR2;
  float D3 = rf[1024 + 4 * k + 3] * IR2;

  float s1[8], s2[8], s3[8];
#pragma unroll
  for (int j = 0; j < 8; j++) {
    float Ej = (j < 4) ? E : -E;
    float Cj = (j < 4) ? C0 : C1;
    if ((j & 3) >= 2) Cj = -Cj;
    float Dj = (j >> 1) == 0 ? D0 : ((j >> 1) == 1 ? D1 : ((j >> 1) == 2 ? D2 : D3));
    if (j & 1) Dj = -Dj;
    s1[j] = Ej; s2[j] = Cj; s3[j] = Dj;
  }

  const float4* b0 = (const float4*)bw;
  const float4* b1 = (const float4*)(bw + Dn);
  const float4* b2 = (const float4*)(bw + 2 * Dn);
  const float4* b3 = (const float4*)(bw + 3 * Dn);
  float4* ob = (float4*)(out + ((size_t)b * Sn + (size_t)k * 8) * Dn);

  int c = threadIdx.x;
  float4 w0 = b0[c], w1 = b1[c], w2 = b2[c], w3 = b3[c];
#pragma unroll
  for (int j = 0; j < 8; j++) {
    float4 o;
    o.x = A * w0.x + s1[j] * w1.x + s2[j] * w2.x + s3[j] * w3.x;
    o.y = A * w0.y + s1[j] * w1.y + s2[j] * w2.y + s3[j] * w3.y;
    o.z = A * w0.z + s1[j] * w1.z + s2[j] * w2.z + s3[j] * w3.z;
    o.w = A * w0.w + s1[j] * w1.w + s2[j] * w2.w + s3[j] * w3.w;
    __stcs(ob + j * (Dn / 4) + c, o);
  }
}

// ------------------------------------------------------------------
#define SMEMB ((18 * Sn + 512) * 4)

extern "C" void kernel_launch(void* const* d_in, const int* in_sizes, int n_in,
                              void* d_out, int out_size) {
  const float* x   = (const float*)d_in[0];
  const float* w   = (const float*)d_in[1];
  const float* phi = (const float*)d_in[2];
  const float* bw  = (const float*)d_in[3];
  float* out = (float*)d_out;

  cudaFuncSetAttribute((const void*)kB, cudaFuncAttributeMaxDynamicSharedMemorySize, SMEMB);

  kA<<<Bn * 256, 256>>>(x, w);
  kB<<<Bn, 512, SMEMB>>>(phi);
  kC<<<Bn * 256, 512>>>(bw, out);
}

// round 11
// speedup vs baseline: 3.2633x; 1.0789x over previous
#include <cuda_runtime.h>
#include <math.h>

#define Bn 8
#define Sn 2048
#define Dn 2048
#define SMASK 2047
#define IR2 0.70710678118654752f
#define C22 0.35355339059327379f
#define EPSF 1e-8f
#define CFLF 0.4f
#define SQRTD 45.254833995939045f
#define MW 32

__device__ float g_rho_raw[Bn * Sn];
__device__ float g_pt[Bn * Sn];
__device__ float g_rhof[Bn * Sn];

// ------------------------------------------------------------------
// Compile-time Leray taps L (101) and L^2 taps M (2*MW+1).
// ------------------------------------------------------------------
struct TapsF { float L[101]; };
struct MTapsF { float M[2 * MW + 1]; };

__host__ __device__ constexpr TapsF makeTapsF() {
  double h[103] = {};
  for (int m = -49; m <= 49; m++) {
    int am = m < 0 ? -m : m;
    double term = 1.0;
    for (int i = 0; i < am; i++) term *= 0.5;
    double acc = 0.0;
    for (int k = am; k <= 49; k += 2) {
      acc += term;
      int j = (k + m) / 2;
      term = term * (double)((k + 1) * (k + 2)) / (4.0 * (double)((j + 1) * (k + 1 - j)));
    }
    h[51 + m] = -0.5 * acc;
  }
  TapsF t{};
  for (int m = -50; m <= 50; m++) {
    double v = 2.0 * h[51 + m] - h[51 + m - 1] - h[51 + m + 1];
    t.L[50 + m] = (float)((m == 0 ? 1.0 : 0.0) + v);
  }
  return t;
}

__host__ __device__ constexpr MTapsF makeM() {
  double h[103] = {};
  for (int m = -49; m <= 49; m++) {
    int am = m < 0 ? -m : m;
    double term = 1.0;
    for (int i = 0; i < am; i++) term *= 0.5;
    double acc = 0.0;
    for (int k = am; k <= 49; k += 2) {
      acc += term;
      int j = (k + m) / 2;
      term = term * (double)((k + 1) * (k + 2)) / (4.0 * (double)((j + 1) * (k + 1 - j)));
    }
    h[51 + m] = -0.5 * acc;
  }
  double L[101] = {};
  for (int m = -50; m <= 50; m++) {
    double v = 2.0 * h[51 + m] - h[51 + m - 1] - h[51 + m + 1];
    L[50 + m] = (m == 0 ? 1.0 : 0.0) + v;
  }
  MTapsF t{};
  for (int m = -MW; m <= MW; m++) {
    double acc = 0.0;
    for (int j = -50; j <= 50; j++) {
      int k = m - j;
      if (k >= -50 && k <= 50) acc += L[50 + j] * L[50 + k];
    }
    t.M[MW + m] = (float)acc;
  }
  return t;
}

__constant__ TapsF TAPS = makeTapsF();
__constant__ MTapsF MT = makeM();

// Conv L (101 taps) for outputs q..q+3; float4 loads, window q-52..q+55.
__device__ __forceinline__ void convL4(const float* __restrict__ in, int q, float* o) {
  o[0] = o[1] = o[2] = o[3] = 0.f;
  const int base = q + (Sn - 52);
#pragma unroll
  for (int j = 0; j < 27; j++) {
    int p = (base + 4 * j) & SMASK;
    float4 w = *(const float4*)(in + p);
    const int rel = 4 * j - 52;
#pragma unroll
    for (int comp = 0; comp < 4; comp++) {
      float val = comp == 0 ? w.x : (comp == 1 ? w.y : (comp == 2 ? w.z : w.w));
#pragma unroll
      for (int e = 0; e < 4; e++) {
        const int m = rel + comp - e;
        if (m >= -50 && m <= 50) o[e] = fmaf(TAPS.L[50 + m], val, o[e]);
      }
    }
  }
}

// Conv M = L^2 (65 taps) for outputs q..q+3; float4 loads, window q-32..q+35.
__device__ __forceinline__ void convM4(const float* __restrict__ in, int q, float* o) {
  o[0] = o[1] = o[2] = o[3] = 0.f;
  const int base = q + (Sn - MW);
#pragma unroll
  for (int j = 0; j < 17; j++) {
    int p = (base + 4 * j) & SMASK;
    float4 w = *(const float4*)(in + p);
    const int rel = 4 * j - MW;
#pragma unroll
    for (int comp = 0; comp < 4; comp++) {
      float val = comp == 0 ? w.x : (comp == 1 ? w.y : (comp == 2 ? w.z : w.w));
#pragma unroll
      for (int e = 0; e < 4; e++) {
        const int m = rel + comp - e;
        if (m >= -MW && m <= MW) o[e] = fmaf(MT.M[MW + m], val, o[e]);
      }
    }
  }
}

// ------------------------------------------------------------------
// Kernel A: proven 62-reg version (R9).
// ------------------------------------------------------------------
__global__ void __launch_bounds__(256) kA(const float* __restrict__ x,
                                          const float* __restrict__ w) {
  int blk = blockIdx.x;
  int b = blk >> 8, k = blk & 255;
  const float4* base = (const float4*)(x + ((size_t)b * Sn + (size_t)k * 8) * Dn);
  const float4* w4 = (const float4*)w;

  float acc[16];
#pragma unroll
  for (int q = 0; q < 16; q++) acc[q] = 0.f;

  for (int c = threadIdx.x; c < Dn / 4; c += 256) {
    float4 xr[8];
#pragma unroll
    for (int j = 0; j < 8; j++) xr[j] = __ldcs(base + j * (Dn / 4) + c);
    float4 wv = w4[c];
#pragma unroll
    for (int comp = 0; comp < 4; comp++) {
      float v0 = ((const float*)&xr[0])[comp];
      float v1 = ((const float*)&xr[1])[comp];
      float v2 = ((const float*)&xr[2])[comp];
      float v3 = ((const float*)&xr[3])[comp];
      float v4 = ((const float*)&xr[4])[comp];
      float v5 = ((const float*)&xr[5])[comp];
      float v6 = ((const float*)&xr[6])[comp];
      float v7 = ((const float*)&xr[7])[comp];
      float wc = ((const float*)&wv)[comp];
      float e0 = v0 + v1, e1 = v2 + v3, e2 = v4 + v5, e3 = v6 + v7;
      float d10 = v0 - v1, d11 = v2 - v3, d12 = v4 - v5, d13 = v6 - v7;
      float a20 = e0 + e1, a21 = e2 + e3;
      float d20 = e0 - e1, d21 = e2 - e3;
      float a3 = a20 + a21, d3 = a20 - a21;
      acc[0] += a3 * a3;   acc[1] += d3 * d3;
      acc[2] += d20 * d20; acc[3] += d21 * d21;
      acc[4] += d10 * d10; acc[5] += d11 * d11;
      acc[6] += d12 * d12; acc[7] += d13 * d13;
      acc[8]  += v0 * wc; acc[9]  += v1 * wc; acc[10] += v2 * wc; acc[11] += v3 * wc;
      acc[12] += v4 * wc; acc[13] += v5 * wc; acc[14] += v6 * wc; acc[15] += v7 * wc;
    }
  }

  __shared__ float red[128];
  int lane = threadIdx.x & 31, wid = threadIdx.x >> 5;
#pragma unroll
  for (int q = 0; q < 16; q++) {
    float val = acc[q];
#pragma unroll
    for (int o = 16; o; o >>= 1) val += __shfl_xor_sync(0xffffffffu, val, o);
    if (lane == 0) red[q * 8 + wid] = val;
  }
  __syncthreads();
  if (threadIdx.x < 16) {
    float s2 = 0.f;
#pragma unroll
    for (int ww = 0; ww < 8; ww++) s2 += red[threadIdx.x * 8 + ww];
    int bs = b * Sn;
    int t = threadIdx.x;
    if (t == 0)      g_rho_raw[bs + k]                      = sqrtf(s2) * C22;
    else if (t == 1) g_rho_raw[bs + 256 + k]                = sqrtf(s2) * C22;
    else if (t < 4)  g_rho_raw[bs + 512 + 2 * k + (t - 2)]  = sqrtf(s2) * 0.5f;
    else if (t < 8)  g_rho_raw[bs + 1024 + 4 * k + (t - 4)] = sqrtf(s2) * IR2;
    else             g_pt[bs + 8 * k + (t - 8)] = s2;
  }
}

// ------------------------------------------------------------------
// Reductions for 16 warps.
// ------------------------------------------------------------------
__device__ __forceinline__ void redStoreSum(float v, float* buf, int lane, int wid) {
#pragma unroll
  for (int o = 16; o; o >>= 1) v += __shfl_xor_sync(0xffffffffu, v, o);
  if (lane == 0) buf[wid] = v;
}
__device__ __forceinline__ float readSum16(const float* buf, int lane) {
  float v = buf[lane & 15];
#pragma unroll
  for (int o = 8; o; o >>= 1) v += __shfl_xor_sync(0xffffffffu, v, o);
  return v;
}
__device__ __forceinline__ void redStoreMaxIdx(float v, int idx, float* bv, int* bi,
                                               int lane, int wid) {
#pragma unroll
  for (int o = 16; o; o >>= 1) {
    float ov = __shfl_xor_sync(0xffffffffu, v, o);
    int oi = __shfl_xor_sync(0xffffffffu, idx, o);
    if (ov > v || (ov == v && oi < idx)) { v = ov; idx = oi; }
  }
  if (lane == 0) { bv[wid] = v; bi[wid] = idx; }
}
__device__ __forceinline__ float readMax16(const float* bv, const int* bi, int lane,
                                           int* oi) {
  float v = bv[lane & 15]; int idx = bi[lane & 15];
#pragma unroll
  for (int o = 8; o; o >>= 1) {
    float ov = __shfl_xor_sync(0xffffffffu, v, o);
    int oi2 = __shfl_xor_sync(0xffffffffu, idx, o);
    if (ov > v || (ov == v && oi2 < idx)) { v = ov; idx = oi2; }
  }
  *oi = idx;
  return v;
}

// ------------------------------------------------------------------
// Kernel B: 512 threads, quad layout, fused forward, flux recomputed
// in backward (no Ft arrays).
// ------------------------------------------------------------------
__global__ void __launch_bounds__(512, 1) kB(const float* __restrict__ phi_g) {
  int b = blockIdx.x;
  extern __shared__ float sm[];
  float* phi_s = sm + 0 * Sn;
  float* vv   = sm + 1 * Sn;
  float* rb0  = sm + 2 * Sn;
  float* rb1  = sm + 3 * Sn;
  float* up0  = sm + 4 * Sn;
  float* upA  = sm + 5 * Sn;
  float* upB  = sm + 6 * Sn;
  float* z1   = sm + 7 * Sn;
  float* z2   = sm + 8 * Sn;
  float* z3   = sm + 9 * Sn;
  float* z4   = sm + 10 * Sn;
  float* grA  = sm + 11 * Sn;
  float* grB  = sm + 12 * Sn;
  float* gup  = sm + 13 * Sn;
  float* red  = sm + 14 * Sn;
  float* redMax = red;
  int*   redIdx = (int*)(red + 32);
  float* redSS  = red + 64;            // 4 x 32: raw sums of z~_1..4
  float* dotB0  = red + 192;
  float* dotB1  = red + 224;
  float* redPart = red + 256;
  float* redR   = red + 288;
  float* redF   = red + 320;

  const int tid = threadIdx.x;
  const int lane = tid & 31, wid = tid >> 5;
  const int q = 4 * tid;
  const int pm1 = (q + SMASK) & SMASK;
  const int pp4 = (q + 4) & SMASK;

  // ---- I1 ----
  {
    float4 ph = *(const float4*)(phi_g + q);
    *(float4*)(phi_s + q) = ph;
    float4 rr = *(const float4*)(g_rho_raw + b * Sn + q);
    rr.x += EPSF; rr.y += EPSF; rr.z += EPSF; rr.w += EPSF;
    *(float4*)(rb0 + q) = rr;
  }
  if (tid < 256) {
    const float* p = g_pt + b * Sn + tid * 8;
    float v0 = p[0], v1 = p[1], v2 = p[2], v3 = p[3];
    float v4 = p[4], v5 = p[5], v6 = p[6], v7 = p[7];
    float e0 = v0 + v1, e1 = v2 + v3, e2 = v4 + v5, e3 = v6 + v7;
    float d10 = v0 - v1, d11 = v2 - v3, d12 = v4 - v5, d13 = v6 - v7;
    float a20 = e0 + e1, a21 = e2 + e3;
    float d20 = e0 - e1, d21 = e2 - e3;
    float a3 = a20 + a21, d3 = a20 - a21;
    vv[tid]               = fabsf(a3) * C22 * SQRTD;
    vv[256 + tid]         = fabsf(d3) * C22 * SQRTD;
    vv[512 + 2 * tid]     = fabsf(d20) * 0.5f * SQRTD;
    vv[512 + 2 * tid + 1] = fabsf(d21) * 0.5f * SQRTD;
    vv[1024 + 4 * tid]     = fabsf(d10) * IR2 * SQRTD;
    vv[1024 + 4 * tid + 1] = fabsf(d11) * IR2 * SQRTD;
    vv[1024 + 4 * tid + 2] = fabsf(d12) * IR2 * SQRTD;
    vv[1024 + 4 * tid + 3] = fabsf(d13) * IR2 * SQRTD;
  }
  __syncthreads();
  // ---- I2 ----
  float4 rawq = *(const float4*)(vv + q);
  float rawp = vv[pp4];
  {
    float4 rq = *(const float4*)(rb0 + q);
    redStoreSum((rq.x + rq.y) + (rq.z + rq.w), redF, lane, wid);
    redStoreSum((rawq.x + rawq.y) + (rawq.z + rawq.w) + 4.f * EPSF, redR, lane, wid);
  }
  __syncthreads();
  // ---- I3: normalize v, gup = grad1(v) ----
  float vq0, vq1, vq2, vq3, sd0, sd1, sd2, sd3;
  {
    float inv = 1.f / readSum16(redR, lane);
    vq0 = (rawq.x + EPSF) * inv; vq1 = (rawq.y + EPSF) * inv;
    vq2 = (rawq.z + EPSF) * inv; vq3 = (rawq.w + EPSF) * inv;
    *(float4*)(vv + q) = make_float4(vq0, vq1, vq2, vq3);
    sd0 = (1.f - vq0) * 0.125f; sd1 = (1.f - vq1) * 0.125f;
    sd2 = (1.f - vq2) * 0.125f; sd3 = (1.f - vq3) * 0.125f;
    float4 g = make_float4((rawq.y - rawq.x) * inv, (rawq.z - rawq.y) * inv,
                           (rawq.w - rawq.z) * inv, (rawp - rawq.w) * inv);
    *(float4*)(gup + q) = g;
  }
  __syncthreads();
  // ---- I4b: up0 = L * grad1(v); max ----
  {
    float c[4];
    convL4(gup, q, c);
    *(float4*)(up0 + q) = make_float4(c[0], c[1], c[2], c[3]);
    float mv = -1.f; int mi = 0;
#pragma unroll
    for (int e = 0; e < 4; e++) {
      float a = fabsf(c[e]);
      if (a > mv) { mv = a; mi = q + e; }
    }
    redStoreMaxIdx(mv, mi, redMax, redIdx, lane, wid);
  }
  __syncthreads();

  float dt0 = 0.f; int imax0 = 0;
  float invRho = 0.f, Rho = 0.f, E = 0.f;
  float* rz = rb0;
  float* rzo = rb1;

  for (int ko = 0; ko < 3; ko++) {
    // ---- PR1: reaction ----
    {
      if (ko == 0) {
        int mi; float m = readMax16(redMax, redIdx, lane, &mi);
        dt0 = CFLF / (m + EPSF); imax0 = mi;
      }
      float invR = 1.f / readSum16(redF, lane);
      float4 rq = *(const float4*)(rz + q);
      float4 ph = *(const float4*)(phi_s + q);
      float w0 = rq.x * invR, w1 = rq.y * invR, w2 = rq.z * invR, w3 = rq.w * invR;
      w0 = w0 * expf(-0.1f * (ph.x + logf(w0))) + EPSF;
      w1 = w1 * expf(-0.1f * (ph.y + logf(w1))) + EPSF;
      w2 = w2 * expf(-0.1f * (ph.z + logf(w2))) + EPSF;
      w3 = w3 * expf(-0.1f * (ph.w + logf(w3))) + EPSF;
      *(float4*)(rz + q) = make_float4(w0, w1, w2, w3);
      redStoreSum((w0 + w1) + (w2 + w3), redR, lane, wid);
    }
    __syncthreads();

    float dt = 0.f; int imax = 0;

    for (int it = 0; it < 5; it++) {
      const float* uin = (it == 0) ? up0 : ((it & 1) ? upB : upA);
      float* uout = (it & 1) ? upA : upB;
      float part = 0.f;
      float um, u0, u1, u2, u3, uImaxV;

      // ---- FF: fused forward horizon (4 advect stages, 1 phase) ----
      {
        if (it == 0) {
          Rho = readSum16(redR, lane); invRho = 1.f / Rho;
          E = EPSF * Rho;
          dt = dt0; imax = imax0;
        } else {
          float m = readMax16(redMax, redIdx, lane, &imax);
          dt = CFLF / (m + EPSF);
        }
        float U[12], L[12];
        {
          float4 t = *(const float4*)(uin + ((q + Sn - 4) & SMASK));
          U[0] = t.x; U[1] = t.y; U[2] = t.z; U[3] = t.w;
        }
        {
          float4 t = *(const float4*)(uin + q);
          U[4] = t.x; U[5] = t.y; U[6] = t.z; U[7] = t.w;
        }
        {
          float4 t = *(const float4*)(uin + ((q + 4) & SMASK));
          U[8] = t.x; U[9] = t.y; U[10] = t.z; U[11] = t.w;
        }
        {
          float4 t = *(const float4*)(rz + ((q + Sn - 4) & SMASK));
          L[0] = t.x; L[1] = t.y; L[2] = t.z; L[3] = t.w;
        }
        {
          float4 t = *(const float4*)(rz + q);
          L[4] = t.x; L[5] = t.y; L[6] = t.z; L[7] = t.w;
        }
        {
          float4 t = *(const float4*)(rz + ((q + 4) & SMASK));
          L[8] = t.x; L[9] = t.y; L[10] = t.z; L[11] = t.w;
        }
        um = U[3]; u0 = U[4]; u1 = U[5]; u2 = U[6]; u3 = U[7];
        uImaxV = uin[imax];
        *(float4*)(gup + q) = make_float4(0.f, 0.f, 0.f, 0.f);
        float* zArr[4] = {z1, z2, z3, z4};
#pragma unroll
        for (int h = 0; h < 4; h++) {
          const int lo = 1 + h, hi = 10 - h;
          float F[11], Y[12];
#pragma unroll
          for (int i = 0; i < 11; i++)
            if (i >= lo - 1 && i <= hi)
              F[i] = U[i] > 0.f ? U[i] * L[i] : U[i] * L[i + 1];
#pragma unroll
          for (int i = 0; i < 12; i++)
            if (i >= lo && i <= hi) Y[i] = L[i] - dt * (F[i] - F[i - 1]);
          *(float4*)(zArr[h] + q) = make_float4(Y[4], Y[5], Y[6], Y[7]);
#pragma unroll
          for (int i = 0; i < 12; i++)
            if (i >= lo && i <= hi) L[i] = fabsf(Y[i]) + E;
          redStoreSum((L[4] + L[5]) + (L[6] + L[7]), redSS + 32 * h, lane, wid);
          if (h == 3)
            redStoreSum((sd0 * L[4] + sd1 * L[5]) + (sd2 * L[6] + sd3 * L[7]),
                        dotB1, lane, wid);
        }
      }
      __syncthreads();

      // ---- G3..G0: backward; flux recomputed from z (no Ft arrays) ----
      float S1 = 0.f, S2 = 0.f, S3 = 0.f;
      float iS1 = 0.f, iS2 = 0.f, iS3 = 0.f, iS4 = 0.f;
#pragma unroll
      for (int h = 3; h >= 0; h--) {
        const float* zout = (h == 3) ? z4 : (h == 2 ? z3 : (h == 1 ? z2 : z1));
        const float* zin  = (h == 3) ? z3 : (h == 2 ? z2 : (h == 1 ? z1 : rz));
        const float* grOld = (((h + 1) & 1) ? grB : grA);
        float* grNew = ((h & 1) ? grB : grA);
        const float* dotRd = ((h & 1) ? dotB1 : dotB0);
        float* dotWr = ((h & 1) ? dotB0 : dotB1);

        if (h == 3) {
          S1 = readSum16(redSS + 0, lane);  iS1 = 1.f / S1;
          S2 = readSum16(redSS + 32, lane); iS2 = 1.f / S2;
          S3 = readSum16(redSS + 64, lane); iS3 = 1.f / S3;
          iS4 = 1.f / readSum16(redSS + 96, lane);
        }
        const float iSoutN = (h == 3) ? iS4 : (h == 2 ? iS3 : (h == 1 ? iS2 : iS1));
        const float Sh     = (h == 3) ? S3 : (h == 2 ? S2 : (h == 1 ? S1 : Rho));
        const float iSh    = (h == 3) ? iS3 : (h == 2 ? iS2 : (h == 1 ? iS1 : invRho));
        const float gwScale = Sh * iSoutN;
        float dotv = readSum16(dotRd, lane) * iSoutN;

        // gy at pm1, q..q+3, pp4
        float gy[6];
        {
          float yv[6], gin[6];
          yv[0] = zout[pm1]; yv[5] = zout[pp4];
          float4 zq = *(const float4*)(zout + q);
          yv[1] = zq.x; yv[2] = zq.y; yv[3] = zq.z; yv[4] = zq.w;
          if (h == 3) {
            gin[0] = (1.f - vv[pm1]) * 0.125f;
            gin[5] = (1.f - vv[pp4]) * 0.125f;
            gin[1] = sd0; gin[2] = sd1; gin[3] = sd2; gin[4] = sd3;
          } else {
            gin[0] = grOld[pm1]; gin[5] = grOld[pp4];
            float4 gq = *(const float4*)(grOld + q);
            gin[1] = gq.x; gin[2] = gq.y; gin[3] = gq.z; gin[4] = gq.w;
          }
#pragma unroll
          for (int e = 0; e < 6; e++) {
            float gw = (gin[e] - dotv) * gwScale;
            gy[e] = yv[e] > 0.f ? gw : (yv[e] < 0.f ? -gw : 0.f);
          }
        }

        // L-values of stage h at pm1, quad, pp4 (exactly as FF computed them)
        float Lm1 = zin[pm1], Lp = zin[pp4];
        float4 ziq = *(const float4*)(zin + q);
        float o0, o1, o2, o3;
        if (h == 0) {
          o0 = ziq.x; o1 = ziq.y; o2 = ziq.z; o3 = ziq.w;
        } else {
          o0 = fabsf(ziq.x) + E; o1 = fabsf(ziq.y) + E;
          o2 = fabsf(ziq.z) + E; o3 = fabsf(ziq.w) + E;
          Lm1 = fabsf(Lm1) + E; Lp = fabsf(Lp) + E;
        }
        float r0 = o0 * iSh, r1 = o1 * iSh, r2 = o2 * iSh, r3 = o3 * iSh;
        float rp = Lp * iSh;

        // recompute fluxes (bitwise identical to FF's)
        float Ftm = um > 0.f ? um * Lm1 : um * o0;
        float F0 = u0 > 0.f ? u0 * o0 : u0 * o1;
        float F1 = u1 > 0.f ? u1 * o1 : u1 * o2;
        float F2 = u2 > 0.f ? u2 * o2 : u2 * o3;
        float F3 = u3 > 0.f ? u3 * o3 : u3 * Lp;
        part += iSh * (gy[1] * (Ftm - F0) + gy[2] * (F0 - F1) +
                       gy[3] * (F1 - F2) + gy[4] * (F2 - F3));
        float gFs0 = dt * (gy[2] - gy[1]);
        float gFs1 = dt * (gy[3] - gy[2]);
        float gFs2 = dt * (gy[4] - gy[3]);
        float gFs3 = dt * (gy[5] - gy[4]);
        float gFm0 = dt * (gy[1] - gy[0]);
        {
          float4 gq = *(const float4*)(gup + q);
          gq.x += gFs0 * (u0 > 0.f ? r0 : r1);
          gq.y += gFs1 * (u1 > 0.f ? r1 : r2);
          gq.z += gFs2 * (u2 > 0.f ? r2 : r3);
          gq.w += gFs3 * (u3 > 0.f ? r3 : rp);
          *(float4*)(gup + q) = gq;
        }
        if (h > 0) {
          float ngr0 = gy[1] + (u0 > 0.f ? u0 * gFs0 : 0.f) + (um > 0.f ? 0.f : um * gFm0);
          float ngr1 = gy[2] + (u1 > 0.f ? u1 * gFs1 : 0.f) + (u0 > 0.f ? 0.f : u0 * gFs0);
          float ngr2 = gy[3] + (u2 > 0.f ? u2 * gFs2 : 0.f) + (u1 > 0.f ? 0.f : u1 * gFs1);
          float ngr3 = gy[4] + (u3 > 0.f ? u3 * gFs3 : 0.f) + (u2 > 0.f ? 0.f : u2 * gFs2);
          *(float4*)(grNew + q) = make_float4(ngr0, ngr1, ngr2, ngr3);
          redStoreSum((ngr0 * o0 + ngr1 * o1) + (ngr2 * o2 + ngr3 * o3), dotWr, lane, wid);
        } else {
          redStoreSum(part, redPart, lane, wid);
        }
        __syncthreads();
      }

      // ---- PE': up_{n+1} = up_n - 0.1*M*(gup + argmax corr); max ----
      {
        float gdt = readSum16(redPart, lane);
        float gm = gdt * (-dt * dt * (1.0f / CFLF));
        float sg = uImaxV > 0.f ? 1.f : (uImaxV < 0.f ? -1.f : 0.f);
        float c[4];
        convM4(gup, q, c);
        float uq[4] = {u0, u1, u2, u3};
        float mv = -1.f; int mi = 0;
#pragma unroll
        for (int e = 0; e < 4; e++) {
          int dd = ((imax - (q + e) + 1024) & SMASK) - 1024;
          float corr = (dd >= -MW && dd <= MW) ? gm * sg * MT.M[MW + dd] : 0.f;
          float n = uq[e] - 0.1f * (c[e] + corr);
          c[e] = n;
          float a = fabsf(n);
          if (a > mv) { mv = a; mi = q + e; }
        }
        *(float4*)(uout + q) = make_float4(c[0], c[1], c[2], c[3]);
        redStoreMaxIdx(mv, mi, redMax, redIdx, lane, wid);
      }
      __syncthreads();
    }

    // ---- PF2: outer advect ----
    {
      int mi; float m = readMax16(redMax, redIdx, lane, &mi);
      float dtf = CFLF / (m + EPSF);
      float kap = (ko == 0) ? 0.01f : ((ko == 1) ? 0.005f : 0.0f);
      const float* uf = upB;
      float rm = rz[pm1] * invRho, rp = rz[pp4] * invRho;
      float4 rq = *(const float4*)(rz + q);
      float r0 = rq.x * invRho, r1 = rq.y * invRho, r2 = rq.z * invRho, r3 = rq.w * invRho;
      float um2 = uf[pm1];
      float4 uq = *(const float4*)(uf + q);
      float Fm = um2 > 0.f ? um2 * rm : um2 * r0;
      float F0 = uq.x > 0.f ? uq.x * r0 : uq.x * r1;
      float F1 = uq.y > 0.f ? uq.y * r1 : uq.y * r2;
      float F2 = uq.z > 0.f ? uq.z * r2 : uq.z * r3;
      float F3 = uq.w > 0.f ? uq.w * r3 : uq.w * rp;
      float y0 = r0 - dtf * (F0 - Fm) + kap * dtf * (r1 + rm - 2.f * r0);
      float y1 = r1 - dtf * (F1 - F0) + kap * dtf * (r2 + r0 - 2.f * r1);
      float y2 = r2 - dtf * (F2 - F1) + kap * dtf * (r3 + r1 - 2.f * r2);
      float y3 = r3 - dtf * (F3 - F2) + kap * dtf * (rp + r2 - 2.f * r3);
      float o0 = fabsf(y0) + EPSF, o1 = fabsf(y1) + EPSF;
      float o2 = fabsf(y2) + EPSF, o3 = fabsf(y3) + EPSF;
      *(float4*)(rzo + q) = make_float4(o0, o1, o2, o3);
      redStoreSum((o0 + o1) + (o2 + o3), redF, lane, wid);
    }
    __syncthreads();
    { float* t = rz; rz = rzo; rzo = t; }
  }

  // ---- FO ----
  float t0, t1, t2, t3;
  {
    float invR = 1.f / readSum16(redF, lane);
    float4 rq = *(const float4*)(rz + q);
    t0 = rq.x * invR + 0.1f * vq0;
    t1 = rq.y * invR + 0.1f * vq1;
    t2 = rq.z * invR + 0.1f * vq2;
    t3 = rq.w * invR + 0.1f * vq3;
    redStoreSum((t0 + t1) + (t2 + t3), redR, lane, wid);
  }
  __syncthreads();
  {
    float invSf = 1.f / readSum16(redR, lane);
    *(float4*)(g_rhof + b * Sn + q) =
        make_float4(t0 * invSf, t1 * invSf, t2 * invSf, t3 * invSf);
  }
}

// ------------------------------------------------------------------
// Kernel C: 512 threads, single column pass.
// ------------------------------------------------------------------
__global__ void __launch_bounds__(512) kC(const float* __restrict__ bw,
                                          float* __restrict__ out) {
  int blk = blockIdx.x;
  int b = blk >> 8, k = blk & 255;
  const float* rf = g_rhof + b * Sn;
  float A  = rf[k] * C22;
  float E  = rf[256 + k] * C22;
  float C0 = rf[512 + 2 * k] * 0.5f;
  float C1 = rf[512 + 2 * k + 1] * 0.5f;
  float D0 = rf[1024 + 4 * k] * IR2;
  float D1 = rf[1024 + 4 * k + 1] * IR2;
  float D2 = rf[1024 + 4 * k + 2] * IR2;
  float D3 = rf[1024 + 4 * k + 3] * IR2;

  float s1[8], s2[8], s3[8];
#pragma unroll
  for (int j = 0; j < 8; j++) {
    float Ej = (j < 4) ? E : -E;
    float Cj = (j < 4) ? C0 : C1;
    if ((j & 3) >= 2) Cj = -Cj;
    float Dj = (j >> 1) == 0 ? D0 : ((j >> 1) == 1 ? D1 : ((j >> 1) == 2 ? D2 : D3));
    if (j & 1) Dj = -Dj;
    s1[j] = Ej; s2[j] = Cj; s3[j] = Dj;
  }

  const float4* b0 = (const float4*)bw;
  const float4* b1 = (const float4*)(bw + Dn);
  const float4* b2 = (const float4*)(bw + 2 * Dn);
  const float4* b3 = (const float4*)(bw + 3 * Dn);
  float4* ob = (float4*)(out + ((size_t)b * Sn + (size_t)k * 8) * Dn);

  int c = threadIdx.x;
  float4 w0 = b0[c], w1 = b1[c], w2 = b2[c], w3 = b3[c];
#pragma unroll
  for (int j = 0; j < 8; j++) {
    float4 o;
    o.x = A * w0.x + s1[j] * w1.x + s2[j] * w2.x + s3[j] * w3.x;
    o.y = A * w0.y + s1[j] * w1.y + s2[j] * w2.y + s3[j] * w3.y;
    o.z = A * w0.z + s1[j] * w1.z + s2[j] * w2.z + s3[j] * w3.z;
    o.w = A * w0.w + s1[j] * w1.w + s2[j] * w2.w + s3[j] * w3.w;
    __stcs(ob + j * (Dn / 4) + c, o);
  }
}

// ------------------------------------------------------------------
#define SMEMB ((14 * Sn + 512) * 4)

extern "C" void kernel_launch(void* const* d_in, const int* in_sizes, int n_in,
                              void* d_out, int out_size) {
  const float* x   = (const float*)d_in[0];
  const float* w   = (const float*)d_in[1];
  const float* phi = (const float*)d_in[2];
  const float* bw  = (const float*)d_in[3];
  float* out = (float*)d_out;

  cudaFuncSetAttribute((const void*)kB, cudaFuncAttributeMaxDynamicSharedMemorySize, SMEMB);

  kA<<<Bn * 256, 256>>>(x, w);
  kB<<<Bn, 512, SMEMB>>>(phi);
  kC<<<Bn * 256, 512>>>(bw, out);
}